// round 10
// baseline (speedup 1.0000x reference)
#include <cuda_runtime.h>
#include <cuda_fp16.h>
#include <cstdint>

#define BB 8
#define NN 160
#define DD 128
#define HH 8
#define ROWS_TOTAL (BB*NN*NN)   // 204800

// ---------------- scratch ----------------
__device__ float g_s_in [ROWS_TOTAL*HH];     // [b, j, h, i] contiguous in i
__device__ float g_s_out[ROWS_TOTAL*HH];     // [b, i, h, j] contiguous in j
__device__ float g_oi[BB*NN*DD];             // headwise (sum_a E)@Wv (in)
__device__ float g_oo[BB*NN*DD];
__device__ float g_xi[BB*NN*DD];
__device__ float g_xj[BB*NN*DD];
__device__ float g_cbias[DD];
// pre-converted half weights
__device__ __align__(16) __half g_whqk[4][128*136];   // (qi,ki,qo,ko), stride 136
__device__ __align__(16) __half g_wf1[128*512];
__device__ __align__(16) __half g_wf2[512*128];
__device__ __align__(16) __half g_wei[128*128];
__device__ __align__(16) __half g_wej[128*128];
__device__ __align__(16) __half g_wpi[128*128];
__device__ __align__(16) __half g_wpo[128*128];

// ---------------- mma/ldmatrix helpers ----------------
#define MMA_F16(d, a0,a1,a2,a3, b0,b1)                                       \
    asm("mma.sync.aligned.m16n8k16.row.col.f32.f16.f16.f32 "                 \
        "{%0,%1,%2,%3}, {%4,%5,%6,%7}, {%8,%9}, {%0,%1,%2,%3};"              \
        : "+f"(d[0]),"+f"(d[1]),"+f"(d[2]),"+f"(d[3])                        \
        : "r"(a0),"r"(a1),"r"(a2),"r"(a3),"r"(b0),"r"(b1))

__device__ __forceinline__ void ldsm4(uint32_t addr, uint32_t& r0, uint32_t& r1,
                                      uint32_t& r2, uint32_t& r3) {
    asm volatile("ldmatrix.sync.aligned.m8n8.x4.shared.b16 {%0,%1,%2,%3}, [%4];"
                 : "=r"(r0),"=r"(r1),"=r"(r2),"=r"(r3) : "r"(addr));
}
__device__ __forceinline__ void ldsm4t(uint32_t addr, uint32_t& r0, uint32_t& r1,
                                       uint32_t& r2, uint32_t& r3) {
    asm volatile("ldmatrix.sync.aligned.m8n8.x4.trans.shared.b16 {%0,%1,%2,%3}, [%4];"
                 : "=r"(r0),"=r"(r1),"=r"(r2),"=r"(r3) : "r"(addr));
}
__device__ __forceinline__ void cp16(uint32_t dst, const void* src) {
    asm volatile("cp.async.cg.shared.global [%0], [%1], 16;" :: "r"(dst), "l"(src));
}
__device__ __forceinline__ void cp_commit() { asm volatile("cp.async.commit_group;"); }
__device__ __forceinline__ void cp_wait()   { asm volatile("cp.async.wait_group 0;" ::: "memory"); }

// ---------------- precompute kernels ----------------
__global__ void cvtw_kernel(const float* __restrict__ Wqi, const float* __restrict__ Wki,
                            const float* __restrict__ Wqo, const float* __restrict__ Wko,
                            const float* __restrict__ Wf1, const float* __restrict__ Wf2,
                            const float* __restrict__ We,
                            const float* __restrict__ Wpi, const float* __restrict__ Wpo) {
    int t = blockIdx.x * 256 + threadIdx.x;
    int reg = blockIdx.y;
    if (reg < 4) {
        if (t < 16384) {
            const float* src = (reg==0)?Wqi:(reg==1)?Wki:(reg==2)?Wqo:Wko;
            int r = t >> 7, c = t & 127;
            g_whqk[reg][r*136 + c] = __float2half_rn(src[t]);
        }
    } else if (reg == 4) { g_wf1[t] = __float2half_rn(Wf1[t]); }
    else if (reg == 5)   { g_wf2[t] = __float2half_rn(Wf2[t]); }
    else if (reg == 6)   { if (t < 16384) g_wei[t] = __float2half_rn(We[t]); }
    else if (reg == 7)   { if (t < 16384) g_wej[t] = __float2half_rn(We[16384 + t]); }
    else if (reg == 8)   { if (t < 16384) g_wpi[t] = __float2half_rn(Wpi[t]); }
    else                 { if (t < 16384) g_wpo[t] = __float2half_rn(Wpo[t]); }
}

__global__ void cbias_kernel(const float* bvi, const float* Wpi, const float* bpi,
                             const float* bvo, const float* Wpo, const float* bpo) {
    int e = threadIdx.x;
    float s = bpi[e] + bpo[e];
    for (int c = 0; c < 128; c++)
        s += bvi[c]*Wpi[c*128+e] + bvo[c]*Wpo[c*128+e];
    g_cbias[e] = s;
}

// =======================================================================
//  FUSED EDGE q/k kernel (unchanged)
//  smem bytes: W0 [0,34816) W1 [34816,69632) A [69632,104448)
// =======================================================================
__device__ __forceinline__ void prefetch_slab(const __half* src, uint32_t dstb, int tid) {
#pragma unroll
    for (int it = 0; it < 9; it++) {
        int idx = tid + it * 256;
        if (idx < 2176) cp16(dstb + idx*16, src + idx*8);
    }
    cp_commit();
}

__device__ __forceinline__ void qpass(uint32_t Ab, uint32_t Wb, int R0, int C0,
                                      int lm_r, int lm_c, float (&acc)[2][8][4]) {
#pragma unroll
    for (int i = 0; i < 2; i++)
#pragma unroll
        for (int j = 0; j < 8; j++)
#pragma unroll
            for (int t = 0; t < 4; t++) acc[i][j][t] = 0.f;
#pragma unroll 1
    for (int kc = 0; kc < 8; kc++) {
        int k0 = kc * 16;
        uint32_t a[2][4];
#pragma unroll
        for (int i = 0; i < 2; i++)
            ldsm4(Ab + (uint32_t)(((R0 + 16*i + lm_r)*136 + k0 + lm_c)*2),
                  a[i][0], a[i][1], a[i][2], a[i][3]);
        uint32_t b[8][2];
#pragma unroll
        for (int jj = 0; jj < 4; jj++) {
            uint32_t r0,r1,r2,r3;
            ldsm4t(Wb + (uint32_t)(((k0 + lm_r)*136 + C0 + 16*jj + lm_c)*2), r0,r1,r2,r3);
            b[2*jj][0]=r0; b[2*jj][1]=r1; b[2*jj+1][0]=r2; b[2*jj+1][1]=r3;
        }
#pragma unroll
        for (int i = 0; i < 2; i++)
#pragma unroll
            for (int j = 0; j < 8; j++)
                MMA_F16(acc[i][j], a[i][0],a[i][1],a[i][2],a[i][3], b[j][0], b[j][1]);
    }
}

__device__ __forceinline__ void pack_q(const float (&acc)[2][8][4],
                                       const float* __restrict__ bq,
                                       int C0, int tg, uint32_t (&qh)[2][8][2]) {
#pragma unroll
    for (int i = 0; i < 2; i++)
#pragma unroll
        for (int j = 0; j < 8; j++) {
            int colg = C0 + 8*j + 2*tg;
            float bq0 = bq[colg], bq1 = bq[colg+1];
            __half2 lo = __floats2half2_rn(acc[i][j][0]+bq0, acc[i][j][1]+bq1);
            __half2 hi = __floats2half2_rn(acc[i][j][2]+bq0, acc[i][j][3]+bq1);
            qh[i][j][0] = *reinterpret_cast<uint32_t*>(&lo);
            qh[i][j][1] = *reinterpret_cast<uint32_t*>(&hi);
        }
}

__device__ __forceinline__ void kpass_pair(uint32_t Ab, uint32_t Wb,
        const uint32_t (&qh)[2][8][2],
        const float* __restrict__ bk,
        float* __restrict__ sdst, int swap,
        int rowbase, int R0, int C0, int g, int tg, int lm_r, int lm_c) {
#pragma unroll 1
    for (int op = 0; op < 2; op++) {
        float acck[2][4][4];
#pragma unroll
        for (int i = 0; i < 2; i++)
#pragma unroll
            for (int j = 0; j < 4; j++)
#pragma unroll
                for (int t = 0; t < 4; t++) acck[i][j][t] = 0.f;
#pragma unroll 1
        for (int kc = 0; kc < 8; kc++) {
            int k0 = kc * 16;
            uint32_t a[2][4];
#pragma unroll
            for (int i = 0; i < 2; i++)
                ldsm4(Ab + (uint32_t)(((R0 + 16*i + lm_r)*136 + k0 + lm_c)*2),
                      a[i][0], a[i][1], a[i][2], a[i][3]);
#pragma unroll
            for (int p = 0; p < 2; p++) {
                int jj = 2*op + p;
                uint32_t b0,b1,b2,b3;
                ldsm4t(Wb + (uint32_t)(((k0 + lm_r)*136 + C0 + 16*jj + lm_c)*2), b0,b1,b2,b3);
#pragma unroll
                for (int i = 0; i < 2; i++) {
                    MMA_F16(acck[i][2*p],   a[i][0],a[i][1],a[i][2],a[i][3], b0, b1);
                    MMA_F16(acck[i][2*p+1], a[i][0],a[i][1],a[i][2],a[i][3], b2, b3);
                }
            }
        }
#pragma unroll
        for (int i = 0; i < 2; i++)
#pragma unroll
            for (int p = 0; p < 2; p++) {
                float sc0 = 0.f, sc1 = 0.f;
#pragma unroll
                for (int j2 = 0; j2 < 2; j2++) {
                    int colg = C0 + 16*(2*op+p) + 8*j2 + 2*tg;
                    float bk0 = bk[colg], bk1 = bk[colg+1];
                    const uint32_t* q = qh[i][4*op + 2*p + j2];
                    float2 qlo = __half22float2(*reinterpret_cast<const __half2*>(&q[0]));
                    float2 qhi = __half22float2(*reinterpret_cast<const __half2*>(&q[1]));
                    const float* k = acck[i][2*p + j2];
                    sc0 += qlo.x*(k[0]+bk0) + qlo.y*(k[1]+bk1);
                    sc1 += qhi.x*(k[2]+bk0) + qhi.y*(k[3]+bk1);
                }
                sc0 += __shfl_xor_sync(0xffffffffu, sc0, 1);
                sc0 += __shfl_xor_sync(0xffffffffu, sc0, 2);
                sc1 += __shfl_xor_sync(0xffffffffu, sc1, 1);
                sc1 += __shfl_xor_sync(0xffffffffu, sc1, 2);
                if (tg == 0) {
                    int h = (C0 >> 4) + 2*op + p;
#pragma unroll
                    for (int hf = 0; hf < 2; hf++) {
                        float v = hf ? sc1 : sc0;
                        int grow = rowbase + R0 + 16*i + 8*hf + g;
                        int b = grow / (NN*NN);
                        int rem = grow - b*NN*NN;
                        int ii = rem / NN;
                        int jn = rem - ii*NN;
                        int r1 = swap ? jn : ii;
                        int r2 = swap ? ii : jn;
                        sdst[((b*NN + r1)*HH + h)*NN + r2] = v * 0.25f;
                    }
                }
            }
    }
}

__global__ void __launch_bounds__(256, 2) fused_edge_kernel(
    const float* __restrict__ edge,
    const float* __restrict__ bqi, const float* __restrict__ bki,
    const float* __restrict__ bqo, const float* __restrict__ bko)
{
    extern __shared__ __half smh[];
    uint32_t sb = (uint32_t)__cvta_generic_to_shared(smh);
    uint32_t W0b = sb, W1b = sb + 34816, Ab = sb + 69632;
    __half* A_h = smh + 34816;

    int tid = threadIdx.x, lane = tid & 31, wid = tid >> 5;
    int g = lane >> 2, tg = lane & 3;
    int lm_r = ((lane >> 3) & 1) * 8 + (lane & 7);
    int lm_c = (lane >> 4) * 8;
    int R0 = (wid >> 1) * 32, C0 = (wid & 1) * 64;
    int rowbase = blockIdx.x * 128;

    prefetch_slab(g_whqk[0], W0b, tid);

    const float4* Eg = (const float4*)(edge + (long)rowbase * DD);
#pragma unroll
    for (int it = 0; it < 16; it++) {
        int idx = tid + it * 256;
        int r = idx >> 5, c4 = idx & 31;
        float4 v = Eg[idx];
        __half2 h01 = __floats2half2_rn(v.x, v.y);
        __half2 h23 = __floats2half2_rn(v.z, v.w);
        uint2 u;
        u.x = *reinterpret_cast<uint32_t*>(&h01);
        u.y = *reinterpret_cast<uint32_t*>(&h23);
        *reinterpret_cast<uint2*>(&A_h[r*136 + c4*4]) = u;
    }
    cp_wait(); __syncthreads();
    prefetch_slab(g_whqk[1], W1b, tid);

    uint32_t qh[2][8][2];
    {
        float accQ[2][8][4];
        qpass(Ab, W0b, R0, C0, lm_r, lm_c, accQ);
        pack_q(accQ, bqi, C0, tg, qh);
    }
    cp_wait(); __syncthreads();
    prefetch_slab(g_whqk[2], W0b, tid);
    kpass_pair(Ab, W1b, qh, bki, g_s_in, 1, rowbase, R0, C0, g, tg, lm_r, lm_c);

    cp_wait(); __syncthreads();
    prefetch_slab(g_whqk[3], W1b, tid);
    {
        float accQ[2][8][4];
        qpass(Ab, W0b, R0, C0, lm_r, lm_c, accQ);
        pack_q(accQ, bqo, C0, tg, qh);
    }
    cp_wait(); __syncthreads();
    kpass_pair(Ab, W1b, qh, bko, g_s_out, 0, rowbase, R0, C0, g, tg, lm_r, lm_c);
}

// =======================================================================
//  wsum: softmax + MMA reduction + fused headwise @Wv  ->  g_oi / g_oo
//  dynamic smem layout (bytes):
//   sE   [0, 43520)            160x136 half
//   sA   [43520, 48896)        16x168 half
//   swe  [48896, 53120)        8x132 float
//   sprt [53120, 53632)        128 float
// =======================================================================
#define WSM_TOTAL 53632

__global__ void __launch_bounds__(256) wsum_kernel(const float* __restrict__ edge,
                                                   const float* __restrict__ Wv,
                                                   int dir) {
    extern __shared__ char wsm[];
    __half* sE  = (__half*)(wsm);
    __half* sA  = (__half*)(wsm + 43520);
    float*  swe = (float*)(wsm + 48896);
    float*  sprt= (float*)(wsm + 53120);
    int tid = threadIdx.x, lane = tid & 31, wid = tid >> 5;
    int bn = blockIdx.x;
    int b = bn / NN, n = bn % NN;

    // load edge slice (160 x 128) as fp16
    long gbase; long rstride;
    if (dir) { gbase = (long)bn * NN * DD;                 rstride = DD; }
    else     { gbase = ((long)b * NN * NN + n) * DD;       rstride = (long)NN * DD; }
#pragma unroll 4
    for (int rr = 0; rr < 20; rr++) {
        int row = wid + rr * 8;
        float4 v = __ldcs((const float4*)&edge[gbase + (long)row * rstride + lane * 4]);
        __half2 h01 = __floats2half2_rn(v.x, v.y);
        __half2 h23 = __floats2half2_rn(v.z, v.w);
        uint2 u;
        u.x = *reinterpret_cast<uint32_t*>(&h01);
        u.y = *reinterpret_cast<uint32_t*>(&h23);
        *reinterpret_cast<uint2*>(&sE[row*136 + lane*4]) = u;
    }

    // softmax: warp wid owns head wid
    {
        const float* s = dir ? g_s_out : g_s_in;
        long sbase = (long)bn * (HH*NN) + (long)wid * NN;
        float v[5];
#pragma unroll
        for (int t = 0; t < 5; t++) v[t] = s[sbase + lane + 32*t];
        float mx = v[0];
#pragma unroll
        for (int t = 1; t < 5; t++) mx = fmaxf(mx, v[t]);
#pragma unroll
        for (int o = 16; o > 0; o >>= 1) mx = fmaxf(mx, __shfl_xor_sync(0xffffffffu, mx, o));
        float sum = 0.f;
#pragma unroll
        for (int t = 0; t < 5; t++) { v[t] = __expf(v[t] - mx); sum += v[t]; }
#pragma unroll
        for (int o = 16; o > 0; o >>= 1) sum += __shfl_xor_sync(0xffffffffu, sum, o);
        float inv = __frcp_rn(sum);
#pragma unroll
        for (int t = 0; t < 5; t++) sA[wid*168 + lane + 32*t] = __float2half_rn(v[t] * inv);
        for (int i = lane; i < 168; i += 32) sA[(wid + 8)*168 + i] = __ushort_as_half(0);
        if (lane < 8) sA[wid*168 + 160 + lane] = __ushort_as_half(0);
    }
    __syncthreads();

    // MMA: warp wid -> we cols [16*wid, 16*wid+16)
    uint32_t Eb = (uint32_t)__cvta_generic_to_shared(sE);
    uint32_t Ab = (uint32_t)__cvta_generic_to_shared(sA);
    int lm_r = ((lane >> 3) & 1) * 8 + (lane & 7);
    int lm_c = (lane >> 4) * 8;
    float acc[2][4];
#pragma unroll
    for (int j = 0; j < 2; j++)
#pragma unroll
        for (int t = 0; t < 4; t++) acc[j][t] = 0.f;
#pragma unroll
    for (int kc = 0; kc < 10; kc++) {
        int k0 = kc * 16;
        uint32_t a0,a1,a2,a3;
        ldsm4(Ab + (uint32_t)((lm_r*168 + k0 + lm_c)*2), a0,a1,a2,a3);
        uint32_t b0,b1,b2,b3;
        ldsm4t(Eb + (uint32_t)(((k0 + lm_r)*136 + wid*16 + lm_c)*2), b0,b1,b2,b3);
        MMA_F16(acc[0], a0,a1,a2,a3, b0,b1);
        MMA_F16(acc[1], a0,a1,a2,a3, b2,b3);
    }
    // we fragment -> swe[head][col]  (row g = head; rows g+8 are zero pad, discard)
    int g = lane >> 2, tg = lane & 3;
#pragma unroll
    for (int j2 = 0; j2 < 2; j2++) {
        int c = wid*16 + 8*j2 + 2*tg;
        swe[g*132 + c]     = acc[j2][0];
        swe[g*132 + c + 1] = acc[j2][1];
    }
    __syncthreads();

    // fused ov: o[e] = sum_k swe[h(e)][k] * Wv[k][e]
    int e = tid & 127, half_ = tid >> 7;
    int h = e >> 4;
    float accv = 0.f;
    int k0 = half_ * 64;
#pragma unroll 8
    for (int k = 0; k < 64; k++) {
        float w = Wv[(k0 + k)*128 + e];
        accv += swe[h*132 + k0 + k] * w;
    }
    if (half_ == 1) sprt[e] = accv;
    __syncthreads();
    if (half_ == 0) {
        float* dst = dir ? g_oo : g_oi;
        dst[(long)bn*128 + e] = accv + sprt[e];
    }
}

// =======================================================================
//  node_chain (unchanged from R9)
// =======================================================================
#define NSM_B    0
#define NSM_A    34816
#define NSM_CS   52224
#define NSM_X1H  86016
#define NSM_X1F  103424
#define NSM_FFH  136192
#define NSM_TOTAL 202752

__device__ __forceinline__ void gmma_g(uint32_t Ab, int astride, uint32_t Bb,
                                       int R0, int C0, int lm_r, int lm_c,
                                       float (&acc)[2][4][4]) {
#pragma unroll 1
    for (int kc = 0; kc < 8; kc++) {
        int k0 = kc * 16;
        uint32_t a[2][4];
#pragma unroll
        for (int i = 0; i < 2; i++)
            ldsm4(Ab + (uint32_t)(((R0 + 16*i + lm_r)*astride + k0 + lm_c)*2),
                  a[i][0], a[i][1], a[i][2], a[i][3]);
        uint32_t b[4][2];
#pragma unroll
        for (int jj = 0; jj < 2; jj++) {
            uint32_t r0,r1,r2,r3;
            ldsm4t(Bb + (uint32_t)(((k0 + lm_r)*136 + C0 + 16*jj + lm_c)*2), r0,r1,r2,r3);
            b[2*jj][0]=r0; b[2*jj][1]=r1; b[2*jj+1][0]=r2; b[2*jj+1][1]=r3;
        }
#pragma unroll
        for (int i = 0; i < 2; i++)
#pragma unroll
            for (int j = 0; j < 4; j++)
                MMA_F16(acc[i][j], a[i][0],a[i][1],a[i][2],a[i][3], b[j][0], b[j][1]);
    }
}

__device__ __forceinline__ void zacc(float (&acc)[2][4][4]) {
#pragma unroll
    for (int i = 0; i < 2; i++)
#pragma unroll
        for (int j = 0; j < 4; j++)
#pragma unroll
            for (int t = 0; t < 4; t++) acc[i][j][t] = 0.f;
}

__global__ void __launch_bounds__(256) node_chain_kernel(
    const float* __restrict__ node,
    const float* __restrict__ bf1, const float* __restrict__ bf2,
    const float* __restrict__ g1,  const float* __restrict__ be1,
    const float* __restrict__ g2,  const float* __restrict__ be2,
    float* __restrict__ out_x)
{
    extern __shared__ char smc[];
    uint32_t sb = (uint32_t)__cvta_generic_to_shared(smc);
    uint32_t Bb = sb + NSM_B, Ab = sb + NSM_A, X1Hb = sb + NSM_X1H, FFHb = sb + NSM_FFH;
    __half* A_h  = (__half*)(smc + NSM_A);
    float*  Cs   = (float*)(smc + NSM_CS);
    __half* x1h  = (__half*)(smc + NSM_X1H);
    float*  x1f  = (float*)(smc + NSM_X1F);
    __half* ffh  = (__half*)(smc + NSM_FFH);
    int tid = threadIdx.x, lane = tid & 31, wid = tid >> 5;
    int g = lane >> 2, tg = lane & 3;
    int lm_r = ((lane >> 3) & 1) * 8 + (lane & 7);
    int lm_c = (lane >> 4) * 8;
    int R0 = (wid >> 2) * 32, C0 = (wid & 3) * 32;
    int rowbase = blockIdx.x * 64;

    float acc[2][4][4];

    // ---- stage A
    zacc(acc);
    for (int c = 0; c < 2; c++) {
        const float* Ap = c ? g_oo : g_oi;
        const __half* Bp = c ? g_wpo : g_wpi;
        if (c) __syncthreads();
#pragma unroll
        for (int it = 0; it < 8; it++) {
            int idx = tid + it * 256;
            int r = idx >> 4, c8 = idx & 15;
            cp16(Bb + (uint32_t)((r*136 + c8*8)*2), Bp + r*128 + c8*8);
        }
        cp_commit();
#pragma unroll
        for (int it = 0; it < 8; it++) {
            int idx = tid + it * 256;
            int r = idx >> 5, c4 = idx & 31;
            float4 v = *(const float4*)&Ap[(long)(rowbase + r)*128 + c4*4];
            __half2 h01 = __floats2half2_rn(v.x, v.y);
            __half2 h23 = __floats2half2_rn(v.z, v.w);
            uint2 u;
            u.x = *reinterpret_cast<uint32_t*>(&h01);
            u.y = *reinterpret_cast<uint32_t*>(&h23);
            *reinterpret_cast<uint2*>(&A_h[r*136 + c4*4]) = u;
        }
        cp_wait();
        __syncthreads();
        gmma_g(Ab, 136, Bb, R0, C0, lm_r, lm_c, acc);
    }
#pragma unroll
    for (int i = 0; i < 2; i++)
#pragma unroll
        for (int j = 0; j < 4; j++) {
            int cl = C0 + 8*j + 2*tg;
            int lr0 = R0 + 16*i + g, lr1 = lr0 + 8;
            float2 n0 = *(const float2*)&node[((long)rowbase + lr0)*128 + cl];
            float2 n1 = *(const float2*)&node[((long)rowbase + lr1)*128 + cl];
            float b0 = g_cbias[cl], b1 = g_cbias[cl+1];
            *(float2*)&Cs[lr0*132 + cl] = make_float2(acc[i][j][0]+b0+n0.x, acc[i][j][1]+b1+n0.y);
            *(float2*)&Cs[lr1*132 + cl] = make_float2(acc[i][j][2]+b0+n1.x, acc[i][j][3]+b1+n1.y);
        }
    __syncthreads();
#pragma unroll
    for (int r = 0; r < 8; r++) {
        int row = wid * 8 + r;
        float4 v = *(const float4*)&Cs[row*132 + lane*4];
        float s = v.x + v.y + v.z + v.w;
#pragma unroll
        for (int o = 16; o > 0; o >>= 1) s += __shfl_xor_sync(0xffffffffu, s, o);
        float mean = s * (1.f/128.f);
        float4 dd = make_float4(v.x-mean, v.y-mean, v.z-mean, v.w-mean);
        float q = dd.x*dd.x + dd.y*dd.y + dd.z*dd.z + dd.w*dd.w;
#pragma unroll
        for (int o = 16; o > 0; o >>= 1) q += __shfl_xor_sync(0xffffffffu, q, o);
        float rs = rsqrtf(q * (1.f/128.f) + 1e-5f);
        float4 gg = ((const float4*)g1)[lane];
        float4 bb = ((const float4*)be1)[lane];
        float4 o4 = make_float4(dd.x*rs*gg.x+bb.x, dd.y*rs*gg.y+bb.y,
                                dd.z*rs*gg.z+bb.z, dd.w*rs*gg.w+bb.w);
        *(float4*)&x1f[row*128 + lane*4] = o4;
        __half2 ha = __floats2half2_rn(o4.x, o4.y);
        __half2 hb = __floats2half2_rn(o4.z, o4.w);
        uint2 u;
        u.x = *reinterpret_cast<uint32_t*>(&ha);
        u.y = *reinterpret_cast<uint32_t*>(&hb);
        *reinterpret_cast<uint2*>(&x1h[row*136 + lane*4]) = u;
    }
    __syncthreads();

    // ---- stage B
    for (int nc = 0; nc < 4; nc++) {
        if (nc) __syncthreads();
#pragma unroll
        for (int it = 0; it < 8; it++) {
            int idx = tid + it * 256;
            int r = idx >> 4, c8 = idx & 15;
            cp16(Bb + (uint32_t)((r*136 + c8*8)*2), g_wf1 + r*512 + nc*128 + c8*8);
        }
        cp_commit(); cp_wait();
        __syncthreads();
        zacc(acc);
        gmma_g(X1Hb, 136, Bb, R0, C0, lm_r, lm_c, acc);
#pragma unroll
        for (int i = 0; i < 2; i++)
#pragma unroll
            for (int j = 0; j < 4; j++) {
                int cl = C0 + 8*j + 2*tg;
                int cg_ = nc*128 + cl;
                float b0 = bf1[cg_], b1 = bf1[cg_+1];
                int lr0 = R0 + 16*i + g, lr1 = lr0 + 8;
                __half2 v0 = __floats2half2_rn(fmaxf(acc[i][j][0]+b0, 0.f), fmaxf(acc[i][j][1]+b1, 0.f));
                __half2 v1 = __floats2half2_rn(fmaxf(acc[i][j][2]+b0, 0.f), fmaxf(acc[i][j][3]+b1, 0.f));
                *reinterpret_cast<uint32_t*>(&ffh[lr0*520 + cg_]) = *reinterpret_cast<uint32_t*>(&v0);
                *reinterpret_cast<uint32_t*>(&ffh[lr1*520 + cg_]) = *reinterpret_cast<uint32_t*>(&v1);
            }
    }
    __syncthreads();

    // ---- stage C
    zacc(acc);
    for (int c = 0; c < 4; c++) {
        int kb = c << 7;
        __syncthreads();
#pragma unroll
        for (int it = 0; it < 8; it++) {
            int idx = tid + it * 256;
            int r = idx >> 4, c8 = idx & 15;
            cp16(Bb + (uint32_t)((r*136 + c8*8)*2), g_wf2 + (long)(kb + r)*128 + c8*8);
        }
        cp_commit(); cp_wait();
        __syncthreads();
        gmma_g(FFHb + (uint32_t)(kb*2), 520, Bb, R0, C0, lm_r, lm_c, acc);
    }
#pragma unroll
    for (int i = 0; i < 2; i++)
#pragma unroll
        for (int j = 0; j < 4; j++) {
            int cl = C0 + 8*j + 2*tg;
            float b0 = bf2[cl], b1 = bf2[cl+1];
            int lr0 = R0 + 16*i + g, lr1 = lr0 + 8;
            float2 r0v = *(const float2*)&x1f[lr0*128 + cl];
            float2 r1v = *(const float2*)&x1f[lr1*128 + cl];
            *(float2*)&Cs[lr0*132 + cl] = make_float2(acc[i][j][0]+b0+r0v.x, acc[i][j][1]+b1+r0v.y);
            *(float2*)&Cs[lr1*132 + cl] = make_float2(acc[i][j][2]+b0+r1v.x, acc[i][j][3]+b1+r1v.y);
        }
    __syncthreads();
#pragma unroll
    for (int r = 0; r < 8; r++) {
        int row = wid * 8 + r;
        float4 v = *(const float4*)&Cs[row*132 + lane*4];
        float s = v.x + v.y + v.z + v.w;
#pragma unroll
        for (int o = 16; o > 0; o >>= 1) s += __shfl_xor_sync(0xffffffffu, s, o);
        float mean = s * (1.f/128.f);
        float4 dd = make_float4(v.x-mean, v.y-mean, v.z-mean, v.w-mean);
        float q = dd.x*dd.x + dd.y*dd.y + dd.z*dd.z + dd.w*dd.w;
#pragma unroll
        for (int o = 16; o > 0; o >>= 1) q += __shfl_xor_sync(0xffffffffu, q, o);
        float rs = rsqrtf(q * (1.f/128.f) + 1e-5f);
        float4 gg = ((const float4*)g2)[lane];
        float4 bb = ((const float4*)be2)[lane];
        float4 o4 = make_float4(dd.x*rs*gg.x+bb.x, dd.y*rs*gg.y+bb.y,
                                dd.z*rs*gg.z+bb.z, dd.w*rs*gg.w+bb.w);
        *(float4*)&out_x[((long)rowbase + row)*128 + lane*4] = o4;
        __half2 ha = __floats2half2_rn(o4.x, o4.y);
        __half2 hb = __floats2half2_rn(o4.z, o4.w);
        uint2 u;
        u.x = *reinterpret_cast<uint32_t*>(&ha);
        u.y = *reinterpret_cast<uint32_t*>(&hb);
        *reinterpret_cast<uint2*>(&x1h[row*136 + lane*4]) = u;
    }
    __syncthreads();

    // ---- stage D
    for (int which = 0; which < 2; which++) {
        if (which) __syncthreads();
#pragma unroll
        for (int it = 0; it < 8; it++) {
            int idx = tid + it * 256;
            int r = idx >> 4, c8 = idx & 15;
            cp16(Bb + (uint32_t)((r*136 + c8*8)*2),
                 (which ? g_wej : g_wei) + r*128 + c8*8);
        }
        cp_commit(); cp_wait();
        __syncthreads();
        zacc(acc);
        gmma_g(X1Hb, 136, Bb, R0, C0, lm_r, lm_c, acc);
        float* dst = which ? g_xj : g_xi;
#pragma unroll
        for (int i = 0; i < 2; i++)
#pragma unroll
            for (int j = 0; j < 4; j++) {
                int cl = C0 + 8*j + 2*tg;
                int lr0 = R0 + 16*i + g, lr1 = lr0 + 8;
                *(float2*)&dst[((long)rowbase + lr0)*128 + cl] = make_float2(acc[i][j][0], acc[i][j][1]);
                *(float2*)&dst[((long)rowbase + lr1)*128 + cl] = make_float2(acc[i][j][2], acc[i][j][3]);
            }
    }
}

// ---------------- edge_out broadcast ----------------
__global__ void edge_out_kernel(const float* __restrict__ b_edge, float* __restrict__ dst) {
    long gid = (long)blockIdx.x * blockDim.x + threadIdx.x;
    int e4 = (int)(gid & 31);
    long rem = gid >> 5;
    int j = (int)(rem % NN);
    long rem2 = rem / NN;
    int i = (int)(rem2 % NN);
    int b = (int)(rem2 / NN);
    float4 xi = ((const float4*)g_xi)[(b * NN + i) * 32 + e4];
    float4 xj = ((const float4*)g_xj)[(b * NN + j) * 32 + e4];
    float4 be = ((const float4*)b_edge)[e4];
    float4 o;
    o.x = xi.x + xj.x + be.x;
    o.y = xi.y + xj.y + be.y;
    o.z = xi.z + xj.z + be.z;
    o.w = xi.w + xj.w + be.w;
    __stcs(&((float4*)dst)[gid], o);
}

// ---------------- launch ----------------
extern "C" void kernel_launch(void* const* d_in, const int* in_sizes, int n_in,
                              void* d_out, int out_size) {
    const float* node   = (const float*)d_in[0];
    const float* edge   = (const float*)d_in[1];
    const float* Wqi = (const float*)d_in[2];  const float* bqi = (const float*)d_in[3];
    const float* Wki = (const float*)d_in[4];  const float* bki = (const float*)d_in[5];
    const float* Wvi = (const float*)d_in[6];  const float* bvi = (const float*)d_in[7];
    const float* Wqo = (const float*)d_in[8];  const float* bqo = (const float*)d_in[9];
    const float* Wko = (const float*)d_in[10]; const float* bko = (const float*)d_in[11];
    const float* Wvo = (const float*)d_in[12]; const float* bvo = (const float*)d_in[13];
    const float* Wpi = (const float*)d_in[14]; const float* bpi = (const float*)d_in[15];
    const float* Wpo = (const float*)d_in[16]; const float* bpo = (const float*)d_in[17];
    const float* Wf1 = (const float*)d_in[18]; const float* bf1 = (const float*)d_in[19];
    const float* Wf2 = (const float*)d_in[20]; const float* bf2 = (const float*)d_in[21];
    const float* g1  = (const float*)d_in[22]; const float* be1 = (const float*)d_in[23];
    const float* g2  = (const float*)d_in[24]; const float* be2 = (const float*)d_in[25];
    const float* Wedge = (const float*)d_in[26];
    const float* bedge = (const float*)d_in[27];
    float* out = (float*)d_out;

    cudaFuncSetAttribute(fused_edge_kernel,
                         cudaFuncAttributeMaxDynamicSharedMemorySize, 104448);
    cudaFuncSetAttribute(wsum_kernel,
                         cudaFuncAttributeMaxDynamicSharedMemorySize, WSM_TOTAL);
    cudaFuncSetAttribute(node_chain_kernel,
                         cudaFuncAttributeMaxDynamicSharedMemorySize, NSM_TOTAL);

    // precompute
    cvtw_kernel<<<dim3(256, 10), 256>>>(Wqi, Wki, Wqo, Wko, Wf1, Wf2, Wedge, Wpi, Wpo);
    cbias_kernel<<<1, 128>>>(bvi, Wpi, bpi, bvo, Wpo, bpo);

    // 1) q/k projections + scores
    fused_edge_kernel<<<ROWS_TOTAL / 128, 256, 104448>>>(edge, bqi, bki, bqo, bko);

    // 2) softmax + weighted edge sums + headwise @Wv (two sequential passes
    //    so the second pass re-reads `edge` through a warm L2)
    wsum_kernel<<<BB * NN, 256, WSM_TOTAL>>>(edge, Wvi, 0);
    wsum_kernel<<<BB * NN, 256, WSM_TOTAL>>>(edge, Wvo, 1);

    // 3) full node chain
    node_chain_kernel<<<BB * NN / 64, 256, NSM_TOTAL>>>(node, bf1, bf2, g1, be1, g2, be2, out);

    // 4) edge_out broadcast
    edge_out_kernel<<<(BB * NN * NN * DD / 4) / 256, 256>>>(bedge, out + BB * NN * DD);
}

// round 11
// speedup vs baseline: 1.0702x; 1.0702x over previous
#include <cuda_runtime.h>
#include <cuda_fp16.h>
#include <cstdint>

#define BB 8
#define NN 160
#define DD 128
#define HH 8
#define ROWS_TOTAL (BB*NN*NN)   // 204800

// ---------------- scratch ----------------
__device__ float g_s_in [ROWS_TOTAL*HH];     // [b, j, h, i] contiguous in i
__device__ float g_s_out[ROWS_TOTAL*HH];     // [b, i, h, j] contiguous in j
__device__ __align__(16) __half g_eh[(long)ROWS_TOTAL*DD];  // fp16 edge (written by fused_edge)
__device__ float g_oi[BB*NN*DD];             // headwise (sum_a E)@Wv (in)
__device__ float g_oo[BB*NN*DD];
__device__ float g_xi[BB*NN*DD];
__device__ float g_xj[BB*NN*DD];
__device__ float g_cbias[DD];
// pre-converted half weights
__device__ __align__(16) __half g_whqk[4][128*136];   // (qi,ki,qo,ko), stride 136
__device__ __align__(16) __half g_wf1[128*512];
__device__ __align__(16) __half g_wf2[512*128];
__device__ __align__(16) __half g_wei[128*128];
__device__ __align__(16) __half g_wej[128*128];
__device__ __align__(16) __half g_wpi[128*128];
__device__ __align__(16) __half g_wpo[128*128];

// ---------------- mma/ldmatrix helpers ----------------
#define MMA_F16(d, a0,a1,a2,a3, b0,b1)                                       \
    asm("mma.sync.aligned.m16n8k16.row.col.f32.f16.f16.f32 "                 \
        "{%0,%1,%2,%3}, {%4,%5,%6,%7}, {%8,%9}, {%0,%1,%2,%3};"              \
        : "+f"(d[0]),"+f"(d[1]),"+f"(d[2]),"+f"(d[3])                        \
        : "r"(a0),"r"(a1),"r"(a2),"r"(a3),"r"(b0),"r"(b1))

__device__ __forceinline__ void ldsm4(uint32_t addr, uint32_t& r0, uint32_t& r1,
                                      uint32_t& r2, uint32_t& r3) {
    asm volatile("ldmatrix.sync.aligned.m8n8.x4.shared.b16 {%0,%1,%2,%3}, [%4];"
                 : "=r"(r0),"=r"(r1),"=r"(r2),"=r"(r3) : "r"(addr));
}
__device__ __forceinline__ void ldsm4t(uint32_t addr, uint32_t& r0, uint32_t& r1,
                                       uint32_t& r2, uint32_t& r3) {
    asm volatile("ldmatrix.sync.aligned.m8n8.x4.trans.shared.b16 {%0,%1,%2,%3}, [%4];"
                 : "=r"(r0),"=r"(r1),"=r"(r2),"=r"(r3) : "r"(addr));
}
__device__ __forceinline__ void cp16(uint32_t dst, const void* src) {
    asm volatile("cp.async.cg.shared.global [%0], [%1], 16;" :: "r"(dst), "l"(src));
}
__device__ __forceinline__ void cp_commit() { asm volatile("cp.async.commit_group;"); }
__device__ __forceinline__ void cp_wait()   { asm volatile("cp.async.wait_group 0;" ::: "memory"); }

// ---------------- precompute kernels ----------------
__global__ void cvtw_kernel(const float* __restrict__ Wqi, const float* __restrict__ Wki,
                            const float* __restrict__ Wqo, const float* __restrict__ Wko,
                            const float* __restrict__ Wf1, const float* __restrict__ Wf2,
                            const float* __restrict__ We,
                            const float* __restrict__ Wpi, const float* __restrict__ Wpo) {
    int t = blockIdx.x * 256 + threadIdx.x;
    int reg = blockIdx.y;
    if (reg < 4) {
        if (t < 16384) {
            const float* src = (reg==0)?Wqi:(reg==1)?Wki:(reg==2)?Wqo:Wko;
            int r = t >> 7, c = t & 127;
            g_whqk[reg][r*136 + c] = __float2half_rn(src[t]);
        }
    } else if (reg == 4) { g_wf1[t] = __float2half_rn(Wf1[t]); }
    else if (reg == 5)   { g_wf2[t] = __float2half_rn(Wf2[t]); }
    else if (reg == 6)   { if (t < 16384) g_wei[t] = __float2half_rn(We[t]); }
    else if (reg == 7)   { if (t < 16384) g_wej[t] = __float2half_rn(We[16384 + t]); }
    else if (reg == 8)   { if (t < 16384) g_wpi[t] = __float2half_rn(Wpi[t]); }
    else                 { if (t < 16384) g_wpo[t] = __float2half_rn(Wpo[t]); }
}

__global__ void cbias_kernel(const float* bvi, const float* Wpi, const float* bpi,
                             const float* bvo, const float* Wpo, const float* bpo) {
    int e = threadIdx.x;
    float s = bpi[e] + bpo[e];
    for (int c = 0; c < 128; c++)
        s += bvi[c]*Wpi[c*128+e] + bvo[c]*Wpo[c*128+e];
    g_cbias[e] = s;
}

// =======================================================================
//  FUSED EDGE q/k kernel + fp16 edge spill to g_eh
//  smem bytes: W0 [0,34816) W1 [34816,69632) A [69632,104448)
// =======================================================================
__device__ __forceinline__ void prefetch_slab(const __half* src, uint32_t dstb, int tid) {
#pragma unroll
    for (int it = 0; it < 9; it++) {
        int idx = tid + it * 256;
        if (idx < 2176) cp16(dstb + idx*16, src + idx*8);
    }
    cp_commit();
}

__device__ __forceinline__ void qpass(uint32_t Ab, uint32_t Wb, int R0, int C0,
                                      int lm_r, int lm_c, float (&acc)[2][8][4]) {
#pragma unroll
    for (int i = 0; i < 2; i++)
#pragma unroll
        for (int j = 0; j < 8; j++)
#pragma unroll
            for (int t = 0; t < 4; t++) acc[i][j][t] = 0.f;
#pragma unroll 1
    for (int kc = 0; kc < 8; kc++) {
        int k0 = kc * 16;
        uint32_t a[2][4];
#pragma unroll
        for (int i = 0; i < 2; i++)
            ldsm4(Ab + (uint32_t)(((R0 + 16*i + lm_r)*136 + k0 + lm_c)*2),
                  a[i][0], a[i][1], a[i][2], a[i][3]);
        uint32_t b[8][2];
#pragma unroll
        for (int jj = 0; jj < 4; jj++) {
            uint32_t r0,r1,r2,r3;
            ldsm4t(Wb + (uint32_t)(((k0 + lm_r)*136 + C0 + 16*jj + lm_c)*2), r0,r1,r2,r3);
            b[2*jj][0]=r0; b[2*jj][1]=r1; b[2*jj+1][0]=r2; b[2*jj+1][1]=r3;
        }
#pragma unroll
        for (int i = 0; i < 2; i++)
#pragma unroll
            for (int j = 0; j < 8; j++)
                MMA_F16(acc[i][j], a[i][0],a[i][1],a[i][2],a[i][3], b[j][0], b[j][1]);
    }
}

__device__ __forceinline__ void pack_q(const float (&acc)[2][8][4],
                                       const float* __restrict__ bq,
                                       int C0, int tg, uint32_t (&qh)[2][8][2]) {
#pragma unroll
    for (int i = 0; i < 2; i++)
#pragma unroll
        for (int j = 0; j < 8; j++) {
            int colg = C0 + 8*j + 2*tg;
            float bq0 = bq[colg], bq1 = bq[colg+1];
            __half2 lo = __floats2half2_rn(acc[i][j][0]+bq0, acc[i][j][1]+bq1);
            __half2 hi = __floats2half2_rn(acc[i][j][2]+bq0, acc[i][j][3]+bq1);
            qh[i][j][0] = *reinterpret_cast<uint32_t*>(&lo);
            qh[i][j][1] = *reinterpret_cast<uint32_t*>(&hi);
        }
}

__device__ __forceinline__ void kpass_pair(uint32_t Ab, uint32_t Wb,
        const uint32_t (&qh)[2][8][2],
        const float* __restrict__ bk,
        float* __restrict__ sdst, int swap,
        int rowbase, int R0, int C0, int g, int tg, int lm_r, int lm_c) {
#pragma unroll 1
    for (int op = 0; op < 2; op++) {
        float acck[2][4][4];
#pragma unroll
        for (int i = 0; i < 2; i++)
#pragma unroll
            for (int j = 0; j < 4; j++)
#pragma unroll
                for (int t = 0; t < 4; t++) acck[i][j][t] = 0.f;
#pragma unroll 1
        for (int kc = 0; kc < 8; kc++) {
            int k0 = kc * 16;
            uint32_t a[2][4];
#pragma unroll
            for (int i = 0; i < 2; i++)
                ldsm4(Ab + (uint32_t)(((R0 + 16*i + lm_r)*136 + k0 + lm_c)*2),
                      a[i][0], a[i][1], a[i][2], a[i][3]);
#pragma unroll
            for (int p = 0; p < 2; p++) {
                int jj = 2*op + p;
                uint32_t b0,b1,b2,b3;
                ldsm4t(Wb + (uint32_t)(((k0 + lm_r)*136 + C0 + 16*jj + lm_c)*2), b0,b1,b2,b3);
#pragma unroll
                for (int i = 0; i < 2; i++) {
                    MMA_F16(acck[i][2*p],   a[i][0],a[i][1],a[i][2],a[i][3], b0, b1);
                    MMA_F16(acck[i][2*p+1], a[i][0],a[i][1],a[i][2],a[i][3], b2, b3);
                }
            }
        }
#pragma unroll
        for (int i = 0; i < 2; i++)
#pragma unroll
            for (int p = 0; p < 2; p++) {
                float sc0 = 0.f, sc1 = 0.f;
#pragma unroll
                for (int j2 = 0; j2 < 2; j2++) {
                    int colg = C0 + 16*(2*op+p) + 8*j2 + 2*tg;
                    float bk0 = bk[colg], bk1 = bk[colg+1];
                    const uint32_t* q = qh[i][4*op + 2*p + j2];
                    float2 qlo = __half22float2(*reinterpret_cast<const __half2*>(&q[0]));
                    float2 qhi = __half22float2(*reinterpret_cast<const __half2*>(&q[1]));
                    const float* k = acck[i][2*p + j2];
                    sc0 += qlo.x*(k[0]+bk0) + qlo.y*(k[1]+bk1);
                    sc1 += qhi.x*(k[2]+bk0) + qhi.y*(k[3]+bk1);
                }
                sc0 += __shfl_xor_sync(0xffffffffu, sc0, 1);
                sc0 += __shfl_xor_sync(0xffffffffu, sc0, 2);
                sc1 += __shfl_xor_sync(0xffffffffu, sc1, 1);
                sc1 += __shfl_xor_sync(0xffffffffu, sc1, 2);
                if (tg == 0) {
                    int h = (C0 >> 4) + 2*op + p;
#pragma unroll
                    for (int hf = 0; hf < 2; hf++) {
                        float v = hf ? sc1 : sc0;
                        int grow = rowbase + R0 + 16*i + 8*hf + g;
                        int b = grow / (NN*NN);
                        int rem = grow - b*NN*NN;
                        int ii = rem / NN;
                        int jn = rem - ii*NN;
                        int r1 = swap ? jn : ii;
                        int r2 = swap ? ii : jn;
                        sdst[((b*NN + r1)*HH + h)*NN + r2] = v * 0.25f;
                    }
                }
            }
    }
}

__global__ void __launch_bounds__(256, 2) fused_edge_kernel(
    const float* __restrict__ edge,
    const float* __restrict__ bqi, const float* __restrict__ bki,
    const float* __restrict__ bqo, const float* __restrict__ bko)
{
    extern __shared__ __half smh[];
    uint32_t sb = (uint32_t)__cvta_generic_to_shared(smh);
    uint32_t W0b = sb, W1b = sb + 34816, Ab = sb + 69632;
    __half* A_h = smh + 34816;

    int tid = threadIdx.x, lane = tid & 31, wid = tid >> 5;
    int g = lane >> 2, tg = lane & 3;
    int lm_r = ((lane >> 3) & 1) * 8 + (lane & 7);
    int lm_c = (lane >> 4) * 8;
    int R0 = (wid >> 1) * 32, C0 = (wid & 1) * 64;
    int rowbase = blockIdx.x * 128;

    prefetch_slab(g_whqk[0], W0b, tid);

    const float4* Eg = (const float4*)(edge + (long)rowbase * DD);
    uint2* Eh = (uint2*)&g_eh[(long)rowbase * DD];
#pragma unroll
    for (int it = 0; it < 16; it++) {
        int idx = tid + it * 256;
        int r = idx >> 5, c4 = idx & 31;
        float4 v = Eg[idx];
        __half2 h01 = __floats2half2_rn(v.x, v.y);
        __half2 h23 = __floats2half2_rn(v.z, v.w);
        uint2 u;
        u.x = *reinterpret_cast<uint32_t*>(&h01);
        u.y = *reinterpret_cast<uint32_t*>(&h23);
        *reinterpret_cast<uint2*>(&A_h[r*136 + c4*4]) = u;
        Eh[idx] = u;               // fp16 edge spill (L2-resident for wsum)
    }
    cp_wait(); __syncthreads();
    prefetch_slab(g_whqk[1], W1b, tid);

    uint32_t qh[2][8][2];
    {
        float accQ[2][8][4];
        qpass(Ab, W0b, R0, C0, lm_r, lm_c, accQ);
        pack_q(accQ, bqi, C0, tg, qh);
    }
    cp_wait(); __syncthreads();
    prefetch_slab(g_whqk[2], W0b, tid);
    kpass_pair(Ab, W1b, qh, bki, g_s_in, 1, rowbase, R0, C0, g, tg, lm_r, lm_c);

    cp_wait(); __syncthreads();
    prefetch_slab(g_whqk[3], W1b, tid);
    {
        float accQ[2][8][4];
        qpass(Ab, W0b, R0, C0, lm_r, lm_c, accQ);
        pack_q(accQ, bqo, C0, tg, qh);
    }
    cp_wait(); __syncthreads();
    kpass_pair(Ab, W1b, qh, bko, g_s_out, 0, rowbase, R0, C0, g, tg, lm_r, lm_c);
}

// =======================================================================
//  wsum: softmax + MMA reduction + fused headwise @Wv  ->  g_oi / g_oo
//  one launch, both directions (grid.y).  Reads fp16 edge from g_eh.
//  smem layout (bytes): sE [0,43520) sA [43520,48896) swe [48896,53120)
//                       sprt [53120,53632)
// =======================================================================
#define WSM_TOTAL 53632

__global__ void __launch_bounds__(256) wsum_kernel(const float* __restrict__ Wvi,
                                                   const float* __restrict__ Wvo) {
    extern __shared__ char wsm[];
    __half* sE  = (__half*)(wsm);
    __half* sA  = (__half*)(wsm + 43520);
    float*  swe = (float*)(wsm + 48896);
    float*  sprt= (float*)(wsm + 53120);
    int tid = threadIdx.x, lane = tid & 31, wid = tid >> 5;
    int bn = blockIdx.x, dir = blockIdx.y;
    int b = bn / NN, n = bn % NN;
    const float* Wv = dir ? Wvo : Wvi;

    // load fp16 edge slice (160 rows x 128 cols); uint2 = 4 halves per lane
    long gbase; long rstride;     // in halves
    if (dir) { gbase = (long)bn * NN * DD;               rstride = DD; }
    else     { gbase = ((long)b * NN * NN + n) * DD;     rstride = (long)NN * DD; }
#pragma unroll 4
    for (int rr = 0; rr < 20; rr++) {
        int row = wid + rr * 8;
        uint2 u = *(const uint2*)&g_eh[gbase + (long)row * rstride + lane * 4];
        *reinterpret_cast<uint2*>(&sE[row*136 + lane*4]) = u;
    }

    // softmax: warp wid owns head wid
    {
        const float* s = dir ? g_s_out : g_s_in;
        long sbase = (long)bn * (HH*NN) + (long)wid * NN;
        float v[5];
#pragma unroll
        for (int t = 0; t < 5; t++) v[t] = s[sbase + lane + 32*t];
        float mx = v[0];
#pragma unroll
        for (int t = 1; t < 5; t++) mx = fmaxf(mx, v[t]);
#pragma unroll
        for (int o = 16; o > 0; o >>= 1) mx = fmaxf(mx, __shfl_xor_sync(0xffffffffu, mx, o));
        float sum = 0.f;
#pragma unroll
        for (int t = 0; t < 5; t++) { v[t] = __expf(v[t] - mx); sum += v[t]; }
#pragma unroll
        for (int o = 16; o > 0; o >>= 1) sum += __shfl_xor_sync(0xffffffffu, sum, o);
        float inv = __frcp_rn(sum);
#pragma unroll
        for (int t = 0; t < 5; t++) sA[wid*168 + lane + 32*t] = __float2half_rn(v[t] * inv);
        for (int i = lane; i < 168; i += 32) sA[(wid + 8)*168 + i] = __ushort_as_half(0);
        if (lane < 8) sA[wid*168 + 160 + lane] = __ushort_as_half(0);
    }
    __syncthreads();

    // MMA: warp wid -> we cols [16*wid, 16*wid+16)
    uint32_t Eb = (uint32_t)__cvta_generic_to_shared(sE);
    uint32_t Ab = (uint32_t)__cvta_generic_to_shared(sA);
    int lm_r = ((lane >> 3) & 1) * 8 + (lane & 7);
    int lm_c = (lane >> 4) * 8;
    float acc[2][4];
#pragma unroll
    for (int j = 0; j < 2; j++)
#pragma unroll
        for (int t = 0; t < 4; t++) acc[j][t] = 0.f;
#pragma unroll
    for (int kc = 0; kc < 10; kc++) {
        int k0 = kc * 16;
        uint32_t a0,a1,a2,a3;
        ldsm4(Ab + (uint32_t)((lm_r*168 + k0 + lm_c)*2), a0,a1,a2,a3);
        uint32_t b0,b1,b2,b3;
        ldsm4t(Eb + (uint32_t)(((k0 + lm_r)*136 + wid*16 + lm_c)*2), b0,b1,b2,b3);
        MMA_F16(acc[0], a0,a1,a2,a3, b0,b1);
        MMA_F16(acc[1], a0,a1,a2,a3, b2,b3);
    }
    int g = lane >> 2, tg = lane & 3;
#pragma unroll
    for (int j2 = 0; j2 < 2; j2++) {
        int c = wid*16 + 8*j2 + 2*tg;
        swe[g*132 + c]     = acc[j2][0];
        swe[g*132 + c + 1] = acc[j2][1];
    }
    __syncthreads();

    // fused ov: o[e] = sum_k swe[h(e)][k] * Wv[k][e]
    int e = tid & 127, half_ = tid >> 7;
    int h = e >> 4;
    float accv = 0.f;
    int k0 = half_ * 64;
#pragma unroll 8
    for (int k = 0; k < 64; k++) {
        float w = Wv[(k0 + k)*128 + e];
        accv += swe[h*132 + k0 + k] * w;
    }
    if (half_ == 1) sprt[e] = accv;
    __syncthreads();
    if (half_ == 0) {
        float* dst = dir ? g_oo : g_oi;
        dst[(long)bn*128 + e] = accv + sprt[e];
    }
}

// =======================================================================
//  node_chain (unchanged)
// =======================================================================
#define NSM_B    0
#define NSM_A    34816
#define NSM_CS   52224
#define NSM_X1H  86016
#define NSM_X1F  103424
#define NSM_FFH  136192
#define NSM_TOTAL 202752

__device__ __forceinline__ void gmma_g(uint32_t Ab, int astride, uint32_t Bb,
                                       int R0, int C0, int lm_r, int lm_c,
                                       float (&acc)[2][4][4]) {
#pragma unroll 1
    for (int kc = 0; kc < 8; kc++) {
        int k0 = kc * 16;
        uint32_t a[2][4];
#pragma unroll
        for (int i = 0; i < 2; i++)
            ldsm4(Ab + (uint32_t)(((R0 + 16*i + lm_r)*astride + k0 + lm_c)*2),
                  a[i][0], a[i][1], a[i][2], a[i][3]);
        uint32_t b[4][2];
#pragma unroll
        for (int jj = 0; jj < 2; jj++) {
            uint32_t r0,r1,r2,r3;
            ldsm4t(Bb + (uint32_t)(((k0 + lm_r)*136 + C0 + 16*jj + lm_c)*2), r0,r1,r2,r3);
            b[2*jj][0]=r0; b[2*jj][1]=r1; b[2*jj+1][0]=r2; b[2*jj+1][1]=r3;
        }
#pragma unroll
        for (int i = 0; i < 2; i++)
#pragma unroll
            for (int j = 0; j < 4; j++)
                MMA_F16(acc[i][j], a[i][0],a[i][1],a[i][2],a[i][3], b[j][0], b[j][1]);
    }
}

__device__ __forceinline__ void zacc(float (&acc)[2][4][4]) {
#pragma unroll
    for (int i = 0; i < 2; i++)
#pragma unroll
        for (int j = 0; j < 4; j++)
#pragma unroll
            for (int t = 0; t < 4; t++) acc[i][j][t] = 0.f;
}

__global__ void __launch_bounds__(256) node_chain_kernel(
    const float* __restrict__ node,
    const float* __restrict__ bf1, const float* __restrict__ bf2,
    const float* __restrict__ g1,  const float* __restrict__ be1,
    const float* __restrict__ g2,  const float* __restrict__ be2,
    float* __restrict__ out_x)
{
    extern __shared__ char smc[];
    uint32_t sb = (uint32_t)__cvta_generic_to_shared(smc);
    uint32_t Bb = sb + NSM_B, Ab = sb + NSM_A, X1Hb = sb + NSM_X1H, FFHb = sb + NSM_FFH;
    __half* A_h  = (__half*)(smc + NSM_A);
    float*  Cs   = (float*)(smc + NSM_CS);
    __half* x1h  = (__half*)(smc + NSM_X1H);
    float*  x1f  = (float*)(smc + NSM_X1F);
    __half* ffh  = (__half*)(smc + NSM_FFH);
    int tid = threadIdx.x, lane = tid & 31, wid = tid >> 5;
    int g = lane >> 2, tg = lane & 3;
    int lm_r = ((lane >> 3) & 1) * 8 + (lane & 7);
    int lm_c = (lane >> 4) * 8;
    int R0 = (wid >> 2) * 32, C0 = (wid & 3) * 32;
    int rowbase = blockIdx.x * 64;

    float acc[2][4][4];

    // ---- stage A
    zacc(acc);
    for (int c = 0; c < 2; c++) {
        const float* Ap = c ? g_oo : g_oi;
        const __half* Bp = c ? g_wpo : g_wpi;
        if (c) __syncthreads();
#pragma unroll
        for (int it = 0; it < 8; it++) {
            int idx = tid + it * 256;
            int r = idx >> 4, c8 = idx & 15;
            cp16(Bb + (uint32_t)((r*136 + c8*8)*2), Bp + r*128 + c8*8);
        }
        cp_commit();
#pragma unroll
        for (int it = 0; it < 8; it++) {
            int idx = tid + it * 256;
            int r = idx >> 5, c4 = idx & 31;
            float4 v = *(const float4*)&Ap[(long)(rowbase + r)*128 + c4*4];
            __half2 h01 = __floats2half2_rn(v.x, v.y);
            __half2 h23 = __floats2half2_rn(v.z, v.w);
            uint2 u;
            u.x = *reinterpret_cast<uint32_t*>(&h01);
            u.y = *reinterpret_cast<uint32_t*>(&h23);
            *reinterpret_cast<uint2*>(&A_h[r*136 + c4*4]) = u;
        }
        cp_wait();
        __syncthreads();
        gmma_g(Ab, 136, Bb, R0, C0, lm_r, lm_c, acc);
    }
#pragma unroll
    for (int i = 0; i < 2; i++)
#pragma unroll
        for (int j = 0; j < 4; j++) {
            int cl = C0 + 8*j + 2*tg;
            int lr0 = R0 + 16*i + g, lr1 = lr0 + 8;
            float2 n0 = *(const float2*)&node[((long)rowbase + lr0)*128 + cl];
            float2 n1 = *(const float2*)&node[((long)rowbase + lr1)*128 + cl];
            float b0 = g_cbias[cl], b1 = g_cbias[cl+1];
            *(float2*)&Cs[lr0*132 + cl] = make_float2(acc[i][j][0]+b0+n0.x, acc[i][j][1]+b1+n0.y);
            *(float2*)&Cs[lr1*132 + cl] = make_float2(acc[i][j][2]+b0+n1.x, acc[i][j][3]+b1+n1.y);
        }
    __syncthreads();
#pragma unroll
    for (int r = 0; r < 8; r++) {
        int row = wid * 8 + r;
        float4 v = *(const float4*)&Cs[row*132 + lane*4];
        float s = v.x + v.y + v.z + v.w;
#pragma unroll
        for (int o = 16; o > 0; o >>= 1) s += __shfl_xor_sync(0xffffffffu, s, o);
        float mean = s * (1.f/128.f);
        float4 dd = make_float4(v.x-mean, v.y-mean, v.z-mean, v.w-mean);
        float q = dd.x*dd.x + dd.y*dd.y + dd.z*dd.z + dd.w*dd.w;
#pragma unroll
        for (int o = 16; o > 0; o >>= 1) q += __shfl_xor_sync(0xffffffffu, q, o);
        float rs = rsqrtf(q * (1.f/128.f) + 1e-5f);
        float4 gg = ((const float4*)g1)[lane];
        float4 bb = ((const float4*)be1)[lane];
        float4 o4 = make_float4(dd.x*rs*gg.x+bb.x, dd.y*rs*gg.y+bb.y,
                                dd.z*rs*gg.z+bb.z, dd.w*rs*gg.w+bb.w);
        *(float4*)&x1f[row*128 + lane*4] = o4;
        __half2 ha = __floats2half2_rn(o4.x, o4.y);
        __half2 hb = __floats2half2_rn(o4.z, o4.w);
        uint2 u;
        u.x = *reinterpret_cast<uint32_t*>(&ha);
        u.y = *reinterpret_cast<uint32_t*>(&hb);
        *reinterpret_cast<uint2*>(&x1h[row*136 + lane*4]) = u;
    }
    __syncthreads();

    // ---- stage B
    for (int nc = 0; nc < 4; nc++) {
        if (nc) __syncthreads();
#pragma unroll
        for (int it = 0; it < 8; it++) {
            int idx = tid + it * 256;
            int r = idx >> 4, c8 = idx & 15;
            cp16(Bb + (uint32_t)((r*136 + c8*8)*2), g_wf1 + r*512 + nc*128 + c8*8);
        }
        cp_commit(); cp_wait();
        __syncthreads();
        zacc(acc);
        gmma_g(X1Hb, 136, Bb, R0, C0, lm_r, lm_c, acc);
#pragma unroll
        for (int i = 0; i < 2; i++)
#pragma unroll
            for (int j = 0; j < 4; j++) {
                int cl = C0 + 8*j + 2*tg;
                int cg_ = nc*128 + cl;
                float b0 = bf1[cg_], b1 = bf1[cg_+1];
                int lr0 = R0 + 16*i + g, lr1 = lr0 + 8;
                __half2 v0 = __floats2half2_rn(fmaxf(acc[i][j][0]+b0, 0.f), fmaxf(acc[i][j][1]+b1, 0.f));
                __half2 v1 = __floats2half2_rn(fmaxf(acc[i][j][2]+b0, 0.f), fmaxf(acc[i][j][3]+b1, 0.f));
                *reinterpret_cast<uint32_t*>(&ffh[lr0*520 + cg_]) = *reinterpret_cast<uint32_t*>(&v0);
                *reinterpret_cast<uint32_t*>(&ffh[lr1*520 + cg_]) = *reinterpret_cast<uint32_t*>(&v1);
            }
    }
    __syncthreads();

    // ---- stage C
    zacc(acc);
    for (int c = 0; c < 4; c++) {
        int kb = c << 7;
        __syncthreads();
#pragma unroll
        for (int it = 0; it < 8; it++) {
            int idx = tid + it * 256;
            int r = idx >> 4, c8 = idx & 15;
            cp16(Bb + (uint32_t)((r*136 + c8*8)*2), g_wf2 + (long)(kb + r)*128 + c8*8);
        }
        cp_commit(); cp_wait();
        __syncthreads();
        gmma_g(FFHb + (uint32_t)(kb*2), 520, Bb, R0, C0, lm_r, lm_c, acc);
    }
#pragma unroll
    for (int i = 0; i < 2; i++)
#pragma unroll
        for (int j = 0; j < 4; j++) {
            int cl = C0 + 8*j + 2*tg;
            float b0 = bf2[cl], b1 = bf2[cl+1];
            int lr0 = R0 + 16*i + g, lr1 = lr0 + 8;
            float2 r0v = *(const float2*)&x1f[lr0*128 + cl];
            float2 r1v = *(const float2*)&x1f[lr1*128 + cl];
            *(float2*)&Cs[lr0*132 + cl] = make_float2(acc[i][j][0]+b0+r0v.x, acc[i][j][1]+b1+r0v.y);
            *(float2*)&Cs[lr1*132 + cl] = make_float2(acc[i][j][2]+b0+r1v.x, acc[i][j][3]+b1+r1v.y);
        }
    __syncthreads();
#pragma unroll
    for (int r = 0; r < 8; r++) {
        int row = wid * 8 + r;
        float4 v = *(const float4*)&Cs[row*132 + lane*4];
        float s = v.x + v.y + v.z + v.w;
#pragma unroll
        for (int o = 16; o > 0; o >>= 1) s += __shfl_xor_sync(0xffffffffu, s, o);
        float mean = s * (1.f/128.f);
        float4 dd = make_float4(v.x-mean, v.y-mean, v.z-mean, v.w-mean);
        float q = dd.x*dd.x + dd.y*dd.y + dd.z*dd.z + dd.w*dd.w;
#pragma unroll
        for (int o = 16; o > 0; o >>= 1) q += __shfl_xor_sync(0xffffffffu, q, o);
        float rs = rsqrtf(q * (1.f/128.f) + 1e-5f);
        float4 gg = ((const float4*)g2)[lane];
        float4 bb = ((const float4*)be2)[lane];
        float4 o4 = make_float4(dd.x*rs*gg.x+bb.x, dd.y*rs*gg.y+bb.y,
                                dd.z*rs*gg.z+bb.z, dd.w*rs*gg.w+bb.w);
        *(float4*)&out_x[((long)rowbase + row)*128 + lane*4] = o4;
        __half2 ha = __floats2half2_rn(o4.x, o4.y);
        __half2 hb = __floats2half2_rn(o4.z, o4.w);
        uint2 u;
        u.x = *reinterpret_cast<uint32_t*>(&ha);
        u.y = *reinterpret_cast<uint32_t*>(&hb);
        *reinterpret_cast<uint2*>(&x1h[row*136 + lane*4]) = u;
    }
    __syncthreads();

    // ---- stage D
    for (int which = 0; which < 2; which++) {
        if (which) __syncthreads();
#pragma unroll
        for (int it = 0; it < 8; it++) {
            int idx = tid + it * 256;
            int r = idx >> 4, c8 = idx & 15;
            cp16(Bb + (uint32_t)((r*136 + c8*8)*2),
                 (which ? g_wej : g_wei) + r*128 + c8*8);
        }
        cp_commit(); cp_wait();
        __syncthreads();
        zacc(acc);
        gmma_g(X1Hb, 136, Bb, R0, C0, lm_r, lm_c, acc);
        float* dst = which ? g_xj : g_xi;
#pragma unroll
        for (int i = 0; i < 2; i++)
#pragma unroll
            for (int j = 0; j < 4; j++) {
                int cl = C0 + 8*j + 2*tg;
                int lr0 = R0 + 16*i + g, lr1 = lr0 + 8;
                *(float2*)&dst[((long)rowbase + lr0)*128 + cl] = make_float2(acc[i][j][0], acc[i][j][1]);
                *(float2*)&dst[((long)rowbase + lr1)*128 + cl] = make_float2(acc[i][j][2], acc[i][j][3]);
            }
    }
}

// ---------------- edge_out broadcast ----------------
__global__ void edge_out_kernel(const float* __restrict__ b_edge, float* __restrict__ dst) {
    long gid = (long)blockIdx.x * blockDim.x + threadIdx.x;
    int e4 = (int)(gid & 31);
    long rem = gid >> 5;
    int j = (int)(rem % NN);
    long rem2 = rem / NN;
    int i = (int)(rem2 % NN);
    int b = (int)(rem2 / NN);
    float4 xi = ((const float4*)g_xi)[(b * NN + i) * 32 + e4];
    float4 xj = ((const float4*)g_xj)[(b * NN + j) * 32 + e4];
    float4 be = ((const float4*)b_edge)[e4];
    float4 o;
    o.x = xi.x + xj.x + be.x;
    o.y = xi.y + xj.y + be.y;
    o.z = xi.z + xj.z + be.z;
    o.w = xi.w + xj.w + be.w;
    __stcs(&((float4*)dst)[gid], o);
}

// ---------------- launch ----------------
extern "C" void kernel_launch(void* const* d_in, const int* in_sizes, int n_in,
                              void* d_out, int out_size) {
    const float* node   = (const float*)d_in[0];
    const float* edge   = (const float*)d_in[1];
    const float* Wqi = (const float*)d_in[2];  const float* bqi = (const float*)d_in[3];
    const float* Wki = (const float*)d_in[4];  const float* bki = (const float*)d_in[5];
    const float* Wvi = (const float*)d_in[6];  const float* bvi = (const float*)d_in[7];
    const float* Wqo = (const float*)d_in[8];  const float* bqo = (const float*)d_in[9];
    const float* Wko = (const float*)d_in[10]; const float* bko = (const float*)d_in[11];
    const float* Wvo = (const float*)d_in[12]; const float* bvo = (const float*)d_in[13];
    const float* Wpi = (const float*)d_in[14]; const float* bpi = (const float*)d_in[15];
    const float* Wpo = (const float*)d_in[16]; const float* bpo = (const float*)d_in[17];
    const float* Wf1 = (const float*)d_in[18]; const float* bf1 = (const float*)d_in[19];
    const float* Wf2 = (const float*)d_in[20]; const float* bf2 = (const float*)d_in[21];
    const float* g1  = (const float*)d_in[22]; const float* be1 = (const float*)d_in[23];
    const float* g2  = (const float*)d_in[24]; const float* be2 = (const float*)d_in[25];
    const float* Wedge = (const float*)d_in[26];
    const float* bedge = (const float*)d_in[27];
    float* out = (float*)d_out;

    cudaFuncSetAttribute(fused_edge_kernel,
                         cudaFuncAttributeMaxDynamicSharedMemorySize, 104448);
    cudaFuncSetAttribute(wsum_kernel,
                         cudaFuncAttributeMaxDynamicSharedMemorySize, WSM_TOTAL);
    cudaFuncSetAttribute(node_chain_kernel,
                         cudaFuncAttributeMaxDynamicSharedMemorySize, NSM_TOTAL);

    // precompute
    cvtw_kernel<<<dim3(256, 10), 256>>>(Wqi, Wki, Wqo, Wko, Wf1, Wf2, Wedge, Wpi, Wpo);
    cbias_kernel<<<1, 128>>>(bvi, Wpi, bpi, bvo, Wpo, bpo);

    // 1) q/k projections + scores + fp16 edge spill
    fused_edge_kernel<<<ROWS_TOTAL / 128, 256, 104448>>>(edge, bqi, bki, bqo, bko);

    // 2) softmax + weighted edge sums + headwise @Wv (both directions, one launch)
    wsum_kernel<<<dim3(BB * NN, 2), 256, WSM_TOTAL>>>(Wvi, Wvo);

    // 3) full node chain
    node_chain_kernel<<<BB * NN / 64, 256, NSM_TOTAL>>>(node, bf1, bf2, g1, be1, g2, be2, out);

    // 4) edge_out broadcast
    edge_out_kernel<<<(BB * NN * NN * DD / 4) / 256, 256>>>(bedge, out + BB * NN * DD);
}

// round 13
// speedup vs baseline: 1.1203x; 1.0469x over previous
#include <cuda_runtime.h>
#include <cuda_fp16.h>
#include <cstdint>

#define BB 8
#define NN 160
#define DD 128
#define HH 8
#define ROWS_TOTAL (BB*NN*NN)   // 204800

// ---------------- scratch ----------------
__device__ float g_s_in [ROWS_TOTAL*HH];     // [b, j, h, i] contiguous in i
__device__ float g_s_out[ROWS_TOTAL*HH];     // [b, i, h, j] contiguous in j
__device__ __align__(16) __half g_eh[(long)ROWS_TOTAL*DD];  // fp16 edge (written by fused_edge)
__device__ float g_oi[BB*NN*DD];             // headwise (sum_a E)@Wv (in)
__device__ float g_oo[BB*NN*DD];
__device__ float g_xi[BB*NN*DD];             // includes b_edge (folded at producer)
__device__ float g_xj[BB*NN*DD];
__device__ float g_cbias[DD];
// pre-converted half weights
__device__ __align__(16) __half g_whqk[4][128*136];   // (qi,ki,qo,ko), stride 136
__device__ __align__(16) __half g_wf1[128*512];
__device__ __align__(16) __half g_wf2[512*128];
__device__ __align__(16) __half g_wei[128*128];
__device__ __align__(16) __half g_wej[128*128];
__device__ __align__(16) __half g_wpi[128*128];
__device__ __align__(16) __half g_wpo[128*128];

// ---------------- mma/ldmatrix helpers ----------------
#define MMA_F16(d, a0,a1,a2,a3, b0,b1)                                       \
    asm("mma.sync.aligned.m16n8k16.row.col.f32.f16.f16.f32 "                 \
        "{%0,%1,%2,%3}, {%4,%5,%6,%7}, {%8,%9}, {%0,%1,%2,%3};"              \
        : "+f"(d[0]),"+f"(d[1]),"+f"(d[2]),"+f"(d[3])                        \
        : "r"(a0),"r"(a1),"r"(a2),"r"(a3),"r"(b0),"r"(b1))

__device__ __forceinline__ void ldsm4(uint32_t addr, uint32_t& r0, uint32_t& r1,
                                      uint32_t& r2, uint32_t& r3) {
    asm volatile("ldmatrix.sync.aligned.m8n8.x4.shared.b16 {%0,%1,%2,%3}, [%4];"
                 : "=r"(r0),"=r"(r1),"=r"(r2),"=r"(r3) : "r"(addr));
}
__device__ __forceinline__ void ldsm4t(uint32_t addr, uint32_t& r0, uint32_t& r1,
                                       uint32_t& r2, uint32_t& r3) {
    asm volatile("ldmatrix.sync.aligned.m8n8.x4.trans.shared.b16 {%0,%1,%2,%3}, [%4];"
                 : "=r"(r0),"=r"(r1),"=r"(r2),"=r"(r3) : "r"(addr));
}
__device__ __forceinline__ void cp16(uint32_t dst, const void* src) {
    asm volatile("cp.async.cg.shared.global [%0], [%1], 16;" :: "r"(dst), "l"(src));
}
__device__ __forceinline__ void cp_commit() { asm volatile("cp.async.commit_group;"); }
__device__ __forceinline__ void cp_wait()   { asm volatile("cp.async.wait_group 0;" ::: "memory"); }

// ---------------- precompute kernels ----------------
__global__ void cvtw_kernel(const float* __restrict__ Wqi, const float* __restrict__ Wki,
                            const float* __restrict__ Wqo, const float* __restrict__ Wko,
                            const float* __restrict__ Wf1, const float* __restrict__ Wf2,
                            const float* __restrict__ We,
                            const float* __restrict__ Wpi, const float* __restrict__ Wpo) {
    int t = blockIdx.x * 256 + threadIdx.x;
    int reg = blockIdx.y;
    if (reg < 4) {
        if (t < 16384) {
            const float* src = (reg==0)?Wqi:(reg==1)?Wki:(reg==2)?Wqo:Wko;
            int r = t >> 7, c = t & 127;
            g_whqk[reg][r*136 + c] = __float2half_rn(src[t]);
        }
    } else if (reg == 4) { g_wf1[t] = __float2half_rn(Wf1[t]); }
    else if (reg == 5)   { g_wf2[t] = __float2half_rn(Wf2[t]); }
    else if (reg == 6)   { if (t < 16384) g_wei[t] = __float2half_rn(We[t]); }
    else if (reg == 7)   { if (t < 16384) g_wej[t] = __float2half_rn(We[16384 + t]); }
    else if (reg == 8)   { if (t < 16384) g_wpi[t] = __float2half_rn(Wpi[t]); }
    else                 { if (t < 16384) g_wpo[t] = __float2half_rn(Wpo[t]); }
}

__global__ void cbias_kernel(const float* bvi, const float* Wpi, const float* bpi,
                             const float* bvo, const float* Wpo, const float* bpo) {
    int e = threadIdx.x;
    float s = bpi[e] + bpo[e];
    for (int c = 0; c < 128; c++)
        s += bvi[c]*Wpi[c*128+e] + bvo[c]*Wpo[c*128+e];
    g_cbias[e] = s;
}

// =======================================================================
//  FUSED EDGE q/k kernel + fp16 edge spill to g_eh (unchanged)
//  smem bytes: W0 [0,34816) W1 [34816,69632) A [69632,104448)
// =======================================================================
__device__ __forceinline__ void prefetch_slab(const __half* src, uint32_t dstb, int tid) {
#pragma unroll
    for (int it = 0; it < 9; it++) {
        int idx = tid + it * 256;
        if (idx < 2176) cp16(dstb + idx*16, src + idx*8);
    }
    cp_commit();
}

__device__ __forceinline__ void qpass(uint32_t Ab, uint32_t Wb, int R0, int C0,
                                      int lm_r, int lm_c, float (&acc)[2][8][4]) {
#pragma unroll
    for (int i = 0; i < 2; i++)
#pragma unroll
        for (int j = 0; j < 8; j++)
#pragma unroll
            for (int t = 0; t < 4; t++) acc[i][j][t] = 0.f;
#pragma unroll 1
    for (int kc = 0; kc < 8; kc++) {
        int k0 = kc * 16;
        uint32_t a[2][4];
#pragma unroll
        for (int i = 0; i < 2; i++)
            ldsm4(Ab + (uint32_t)(((R0 + 16*i + lm_r)*136 + k0 + lm_c)*2),
                  a[i][0], a[i][1], a[i][2], a[i][3]);
        uint32_t b[8][2];
#pragma unroll
        for (int jj = 0; jj < 4; jj++) {
            uint32_t r0,r1,r2,r3;
            ldsm4t(Wb + (uint32_t)(((k0 + lm_r)*136 + C0 + 16*jj + lm_c)*2), r0,r1,r2,r3);
            b[2*jj][0]=r0; b[2*jj][1]=r1; b[2*jj+1][0]=r2; b[2*jj+1][1]=r3;
        }
#pragma unroll
        for (int i = 0; i < 2; i++)
#pragma unroll
            for (int j = 0; j < 8; j++)
                MMA_F16(acc[i][j], a[i][0],a[i][1],a[i][2],a[i][3], b[j][0], b[j][1]);
    }
}

__device__ __forceinline__ void pack_q(const float (&acc)[2][8][4],
                                       const float* __restrict__ bq,
                                       int C0, int tg, uint32_t (&qh)[2][8][2]) {
#pragma unroll
    for (int i = 0; i < 2; i++)
#pragma unroll
        for (int j = 0; j < 8; j++) {
            int colg = C0 + 8*j + 2*tg;
            float bq0 = bq[colg], bq1 = bq[colg+1];
            __half2 lo = __floats2half2_rn(acc[i][j][0]+bq0, acc[i][j][1]+bq1);
            __half2 hi = __floats2half2_rn(acc[i][j][2]+bq0, acc[i][j][3]+bq1);
            qh[i][j][0] = *reinterpret_cast<uint32_t*>(&lo);
            qh[i][j][1] = *reinterpret_cast<uint32_t*>(&hi);
        }
}

__device__ __forceinline__ void kpass_pair(uint32_t Ab, uint32_t Wb,
        const uint32_t (&qh)[2][8][2],
        const float* __restrict__ bk,
        float* __restrict__ sdst, int swap,
        int rowbase, int R0, int C0, int g, int tg, int lm_r, int lm_c) {
#pragma unroll 1
    for (int op = 0; op < 2; op++) {
        float acck[2][4][4];
#pragma unroll
        for (int i = 0; i < 2; i++)
#pragma unroll
            for (int j = 0; j < 4; j++)
#pragma unroll
                for (int t = 0; t < 4; t++) acck[i][j][t] = 0.f;
#pragma unroll 1
        for (int kc = 0; kc < 8; kc++) {
            int k0 = kc * 16;
            uint32_t a[2][4];
#pragma unroll
            for (int i = 0; i < 2; i++)
                ldsm4(Ab + (uint32_t)(((R0 + 16*i + lm_r)*136 + k0 + lm_c)*2),
                      a[i][0], a[i][1], a[i][2], a[i][3]);
#pragma unroll
            for (int p = 0; p < 2; p++) {
                int jj = 2*op + p;
                uint32_t b0,b1,b2,b3;
                ldsm4t(Wb + (uint32_t)(((k0 + lm_r)*136 + C0 + 16*jj + lm_c)*2), b0,b1,b2,b3);
#pragma unroll
                for (int i = 0; i < 2; i++) {
                    MMA_F16(acck[i][2*p],   a[i][0],a[i][1],a[i][2],a[i][3], b0, b1);
                    MMA_F16(acck[i][2*p+1], a[i][0],a[i][1],a[i][2],a[i][3], b2, b3);
                }
            }
        }
#pragma unroll
        for (int i = 0; i < 2; i++)
#pragma unroll
            for (int p = 0; p < 2; p++) {
                float sc0 = 0.f, sc1 = 0.f;
#pragma unroll
                for (int j2 = 0; j2 < 2; j2++) {
                    int colg = C0 + 16*(2*op+p) + 8*j2 + 2*tg;
                    float bk0 = bk[colg], bk1 = bk[colg+1];
                    const uint32_t* q = qh[i][4*op + 2*p + j2];
                    float2 qlo = __half22float2(*reinterpret_cast<const __half2*>(&q[0]));
                    float2 qhi = __half22float2(*reinterpret_cast<const __half2*>(&q[1]));
                    const float* k = acck[i][2*p + j2];
                    sc0 += qlo.x*(k[0]+bk0) + qlo.y*(k[1]+bk1);
                    sc1 += qhi.x*(k[2]+bk0) + qhi.y*(k[3]+bk1);
                }
                sc0 += __shfl_xor_sync(0xffffffffu, sc0, 1);
                sc0 += __shfl_xor_sync(0xffffffffu, sc0, 2);
                sc1 += __shfl_xor_sync(0xffffffffu, sc1, 1);
                sc1 += __shfl_xor_sync(0xffffffffu, sc1, 2);
                if (tg == 0) {
                    int h = (C0 >> 4) + 2*op + p;
#pragma unroll
                    for (int hf = 0; hf < 2; hf++) {
                        float v = hf ? sc1 : sc0;
                        int grow = rowbase + R0 + 16*i + 8*hf + g;
                        int b = grow / (NN*NN);
                        int rem = grow - b*NN*NN;
                        int ii = rem / NN;
                        int jn = rem - ii*NN;
                        int r1 = swap ? jn : ii;
                        int r2 = swap ? ii : jn;
                        sdst[((b*NN + r1)*HH + h)*NN + r2] = v * 0.25f;
                    }
                }
            }
    }
}

__global__ void __launch_bounds__(256, 2) fused_edge_kernel(
    const float* __restrict__ edge,
    const float* __restrict__ bqi, const float* __restrict__ bki,
    const float* __restrict__ bqo, const float* __restrict__ bko)
{
    extern __shared__ __half smh[];
    uint32_t sb = (uint32_t)__cvta_generic_to_shared(smh);
    uint32_t W0b = sb, W1b = sb + 34816, Ab = sb + 69632;
    __half* A_h = smh + 34816;

    int tid = threadIdx.x, lane = tid & 31, wid = tid >> 5;
    int g = lane >> 2, tg = lane & 3;
    int lm_r = ((lane >> 3) & 1) * 8 + (lane & 7);
    int lm_c = (lane >> 4) * 8;
    int R0 = (wid >> 1) * 32, C0 = (wid & 1) * 64;
    int rowbase = blockIdx.x * 128;

    prefetch_slab(g_whqk[0], W0b, tid);

    const float4* Eg = (const float4*)(edge + (long)rowbase * DD);
    uint2* Eh = (uint2*)&g_eh[(long)rowbase * DD];
#pragma unroll
    for (int it = 0; it < 16; it++) {
        int idx = tid + it * 256;
        int r = idx >> 5, c4 = idx & 31;
        float4 v = Eg[idx];
        __half2 h01 = __floats2half2_rn(v.x, v.y);
        __half2 h23 = __floats2half2_rn(v.z, v.w);
        uint2 u;
        u.x = *reinterpret_cast<uint32_t*>(&h01);
        u.y = *reinterpret_cast<uint32_t*>(&h23);
        *reinterpret_cast<uint2*>(&A_h[r*136 + c4*4]) = u;
        Eh[idx] = u;               // fp16 edge spill (L2-resident for wsum)
    }
    cp_wait(); __syncthreads();
    prefetch_slab(g_whqk[1], W1b, tid);

    uint32_t qh[2][8][2];
    {
        float accQ[2][8][4];
        qpass(Ab, W0b, R0, C0, lm_r, lm_c, accQ);
        pack_q(accQ, bqi, C0, tg, qh);
    }
    cp_wait(); __syncthreads();
    prefetch_slab(g_whqk[2], W0b, tid);
    kpass_pair(Ab, W1b, qh, bki, g_s_in, 1, rowbase, R0, C0, g, tg, lm_r, lm_c);

    cp_wait(); __syncthreads();
    prefetch_slab(g_whqk[3], W1b, tid);
    {
        float accQ[2][8][4];
        qpass(Ab, W0b, R0, C0, lm_r, lm_c, accQ);
        pack_q(accQ, bqo, C0, tg, qh);
    }
    cp_wait(); __syncthreads();
    kpass_pair(Ab, W1b, qh, bko, g_s_out, 0, rowbase, R0, C0, g, tg, lm_r, lm_c);
}

// =======================================================================
//  wsum: softmax + MMA reduction + fused headwise @Wv  ->  g_oi / g_oo
//  fp16 edge slice loaded via cp.async (rows are 256B contiguous both dirs)
//  smem layout (bytes): sE [0,43520) sA [43520,48896) swe [48896,53120)
//                       sprt [53120,53632)
// =======================================================================
#define WSM_TOTAL 53632

__global__ void __launch_bounds__(256) wsum_kernel(const float* __restrict__ Wvi,
                                                   const float* __restrict__ Wvo) {
    extern __shared__ char wsm[];
    __half* sE  = (__half*)(wsm);
    __half* sA  = (__half*)(wsm + 43520);
    float*  swe = (float*)(wsm + 48896);
    float*  sprt= (float*)(wsm + 53120);
    int tid = threadIdx.x, lane = tid & 31, wid = tid >> 5;
    int bn = blockIdx.x, dir = blockIdx.y;
    int b = bn / NN, n = bn % NN;
    const float* Wv = dir ? Wvo : Wvi;
    uint32_t sEb = (uint32_t)__cvta_generic_to_shared(sE);

    // cp.async edge slice (160 rows x 256B); 2560 16B-chunks, 10 per thread
    long gbase; long rstride;     // in halves
    if (dir) { gbase = (long)bn * NN * DD;               rstride = DD; }
    else     { gbase = ((long)b * NN * NN + n) * DD;     rstride = (long)NN * DD; }
#pragma unroll
    for (int it = 0; it < 10; it++) {
        int idx = tid + it * 256;
        int row = idx >> 4, c8 = idx & 15;
        cp16(sEb + (uint32_t)(row*272 + c8*16),
             &g_eh[gbase + (long)row * rstride + c8*8]);
    }
    cp_commit();

    // softmax: warp wid owns head wid (independent of the cp.async)
    {
        const float* s = dir ? g_s_out : g_s_in;
        long sbase = (long)bn * (HH*NN) + (long)wid * NN;
        float v[5];
#pragma unroll
        for (int t = 0; t < 5; t++) v[t] = s[sbase + lane + 32*t];
        float mx = v[0];
#pragma unroll
        for (int t = 1; t < 5; t++) mx = fmaxf(mx, v[t]);
#pragma unroll
        for (int o = 16; o > 0; o >>= 1) mx = fmaxf(mx, __shfl_xor_sync(0xffffffffu, mx, o));
        float sum = 0.f;
#pragma unroll
        for (int t = 0; t < 5; t++) { v[t] = __expf(v[t] - mx); sum += v[t]; }
#pragma unroll
        for (int o = 16; o > 0; o >>= 1) sum += __shfl_xor_sync(0xffffffffu, sum, o);
        float inv = __frcp_rn(sum);
#pragma unroll
        for (int t = 0; t < 5; t++) sA[wid*168 + lane + 32*t] = __float2half_rn(v[t] * inv);
        for (int i = lane; i < 168; i += 32) sA[(wid + 8)*168 + i] = __ushort_as_half(0);
        if (lane < 8) sA[wid*168 + 160 + lane] = __ushort_as_half(0);
    }
    cp_wait();
    __syncthreads();

    // MMA: warp wid -> we cols [16*wid, 16*wid+16)
    uint32_t Ab = (uint32_t)__cvta_generic_to_shared(sA);
    int lm_r = ((lane >> 3) & 1) * 8 + (lane & 7);
    int lm_c = (lane >> 4) * 8;
    float acc[2][4];
#pragma unroll
    for (int j = 0; j < 2; j++)
#pragma unroll
        for (int t = 0; t < 4; t++) acc[j][t] = 0.f;
#pragma unroll
    for (int kc = 0; kc < 10; kc++) {
        int k0 = kc * 16;
        uint32_t a0,a1,a2,a3;
        ldsm4(Ab + (uint32_t)((lm_r*168 + k0 + lm_c)*2), a0,a1,a2,a3);
        uint32_t b0,b1,b2,b3;
        ldsm4t(sEb + (uint32_t)(((k0 + lm_r)*136 + wid*16 + lm_c)*2), b0,b1,b2,b3);
        MMA_F16(acc[0], a0,a1,a2,a3, b0,b1);
        MMA_F16(acc[1], a0,a1,a2,a3, b2,b3);
    }
    int g = lane >> 2, tg = lane & 3;
#pragma unroll
    for (int j2 = 0; j2 < 2; j2++) {
        int c = wid*16 + 8*j2 + 2*tg;
        swe[g*132 + c]     = acc[j2][0];
        swe[g*132 + c + 1] = acc[j2][1];
    }
    __syncthreads();

    // fused ov: o[e] = sum_k swe[h(e)][k] * Wv[k][e]
    int e = tid & 127, half_ = tid >> 7;
    int h = e >> 4;
    float accv = 0.f;
    int k0 = half_ * 64;
#pragma unroll 8
    for (int k = 0; k < 64; k++) {
        float w = Wv[(k0 + k)*128 + e];
        accv += swe[h*132 + k0 + k] * w;
    }
    if (half_ == 1) sprt[e] = accv;
    __syncthreads();
    if (half_ == 0) {
        float* dst = dir ? g_oo : g_oi;
        dst[(long)bn*128 + e] = accv + sprt[e];
    }
}

// =======================================================================
//  node_chain (stage D folds b_edge into xi)
// =======================================================================
#define NSM_B    0
#define NSM_A    34816
#define NSM_CS   52224
#define NSM_X1H  86016
#define NSM_X1F  103424
#define NSM_FFH  136192
#define NSM_TOTAL 202752

__device__ __forceinline__ void gmma_g(uint32_t Ab, int astride, uint32_t Bb,
                                       int R0, int C0, int lm_r, int lm_c,
                                       float (&acc)[2][4][4]) {
#pragma unroll 1
    for (int kc = 0; kc < 8; kc++) {
        int k0 = kc * 16;
        uint32_t a[2][4];
#pragma unroll
        for (int i = 0; i < 2; i++)
            ldsm4(Ab + (uint32_t)(((R0 + 16*i + lm_r)*astride + k0 + lm_c)*2),
                  a[i][0], a[i][1], a[i][2], a[i][3]);
        uint32_t b[4][2];
#pragma unroll
        for (int jj = 0; jj < 2; jj++) {
            uint32_t r0,r1,r2,r3;
            ldsm4t(Bb + (uint32_t)(((k0 + lm_r)*136 + C0 + 16*jj + lm_c)*2), r0,r1,r2,r3);
            b[2*jj][0]=r0; b[2*jj][1]=r1; b[2*jj+1][0]=r2; b[2*jj+1][1]=r3;
        }
#pragma unroll
        for (int i = 0; i < 2; i++)
#pragma unroll
            for (int j = 0; j < 4; j++)
                MMA_F16(acc[i][j], a[i][0],a[i][1],a[i][2],a[i][3], b[j][0], b[j][1]);
    }
}

__device__ __forceinline__ void zacc(float (&acc)[2][4][4]) {
#pragma unroll
    for (int i = 0; i < 2; i++)
#pragma unroll
        for (int j = 0; j < 4; j++)
#pragma unroll
            for (int t = 0; t < 4; t++) acc[i][j][t] = 0.f;
}

__global__ void __launch_bounds__(256) node_chain_kernel(
    const float* __restrict__ node,
    const float* __restrict__ bf1, const float* __restrict__ bf2,
    const float* __restrict__ g1,  const float* __restrict__ be1,
    const float* __restrict__ g2,  const float* __restrict__ be2,
    const float* __restrict__ bedge,
    float* __restrict__ out_x)
{
    extern __shared__ char smc[];
    uint32_t sb = (uint32_t)__cvta_generic_to_shared(smc);
    uint32_t Bb = sb + NSM_B, Ab = sb + NSM_A, X1Hb = sb + NSM_X1H, FFHb = sb + NSM_FFH;
    __half* A_h  = (__half*)(smc + NSM_A);
    float*  Cs   = (float*)(smc + NSM_CS);
    __half* x1h  = (__half*)(smc + NSM_X1H);
    float*  x1f  = (float*)(smc + NSM_X1F);
    __half* ffh  = (__half*)(smc + NSM_FFH);
    int tid = threadIdx.x, lane = tid & 31, wid = tid >> 5;
    int g = lane >> 2, tg = lane & 3;
    int lm_r = ((lane >> 3) & 1) * 8 + (lane & 7);
    int lm_c = (lane >> 4) * 8;
    int R0 = (wid >> 2) * 32, C0 = (wid & 3) * 32;
    int rowbase = blockIdx.x * 64;

    float acc[2][4][4];

    // ---- stage A
    zacc(acc);
    for (int c = 0; c < 2; c++) {
        const float* Ap = c ? g_oo : g_oi;
        const __half* Bp = c ? g_wpo : g_wpi;
        if (c) __syncthreads();
#pragma unroll
        for (int it = 0; it < 8; it++) {
            int idx = tid + it * 256;
            int r = idx >> 4, c8 = idx & 15;
            cp16(Bb + (uint32_t)((r*136 + c8*8)*2), Bp + r*128 + c8*8);
        }
        cp_commit();
#pragma unroll
        for (int it = 0; it < 8; it++) {
            int idx = tid + it * 256;
            int r = idx >> 5, c4 = idx & 31;
            float4 v = *(const float4*)&Ap[(long)(rowbase + r)*128 + c4*4];
            __half2 h01 = __floats2half2_rn(v.x, v.y);
            __half2 h23 = __floats2half2_rn(v.z, v.w);
            uint2 u;
            u.x = *reinterpret_cast<uint32_t*>(&h01);
            u.y = *reinterpret_cast<uint32_t*>(&h23);
            *reinterpret_cast<uint2*>(&A_h[r*136 + c4*4]) = u;
        }
        cp_wait();
        __syncthreads();
        gmma_g(Ab, 136, Bb, R0, C0, lm_r, lm_c, acc);
    }
#pragma unroll
    for (int i = 0; i < 2; i++)
#pragma unroll
        for (int j = 0; j < 4; j++) {
            int cl = C0 + 8*j + 2*tg;
            int lr0 = R0 + 16*i + g, lr1 = lr0 + 8;
            float2 n0 = *(const float2*)&node[((long)rowbase + lr0)*128 + cl];
            float2 n1 = *(const float2*)&node[((long)rowbase + lr1)*128 + cl];
            float b0 = g_cbias[cl], b1 = g_cbias[cl+1];
            *(float2*)&Cs[lr0*132 + cl] = make_float2(acc[i][j][0]+b0+n0.x, acc[i][j][1]+b1+n0.y);
            *(float2*)&Cs[lr1*132 + cl] = make_float2(acc[i][j][2]+b0+n1.x, acc[i][j][3]+b1+n1.y);
        }
    __syncthreads();
#pragma unroll
    for (int r = 0; r < 8; r++) {
        int row = wid * 8 + r;
        float4 v = *(const float4*)&Cs[row*132 + lane*4];
        float s = v.x + v.y + v.z + v.w;
#pragma unroll
        for (int o = 16; o > 0; o >>= 1) s += __shfl_xor_sync(0xffffffffu, s, o);
        float mean = s * (1.f/128.f);
        float4 dd = make_float4(v.x-mean, v.y-mean, v.z-mean, v.w-mean);
        float q = dd.x*dd.x + dd.y*dd.y + dd.z*dd.z + dd.w*dd.w;
#pragma unroll
        for (int o = 16; o > 0; o >>= 1) q += __shfl_xor_sync(0xffffffffu, q, o);
        float rs = rsqrtf(q * (1.f/128.f) + 1e-5f);
        float4 gg = ((const float4*)g1)[lane];
        float4 bb = ((const float4*)be1)[lane];
        float4 o4 = make_float4(dd.x*rs*gg.x+bb.x, dd.y*rs*gg.y+bb.y,
                                dd.z*rs*gg.z+bb.z, dd.w*rs*gg.w+bb.w);
        *(float4*)&x1f[row*128 + lane*4] = o4;
        __half2 ha = __floats2half2_rn(o4.x, o4.y);
        __half2 hb = __floats2half2_rn(o4.z, o4.w);
        uint2 u;
        u.x = *reinterpret_cast<uint32_t*>(&ha);
        u.y = *reinterpret_cast<uint32_t*>(&hb);
        *reinterpret_cast<uint2*>(&x1h[row*136 + lane*4]) = u;
    }
    __syncthreads();

    // ---- stage B
    for (int nc = 0; nc < 4; nc++) {
        if (nc) __syncthreads();
#pragma unroll
        for (int it = 0; it < 8; it++) {
            int idx = tid + it * 256;
            int r = idx >> 4, c8 = idx & 15;
            cp16(Bb + (uint32_t)((r*136 + c8*8)*2), g_wf1 + r*512 + nc*128 + c8*8);
        }
        cp_commit(); cp_wait();
        __syncthreads();
        zacc(acc);
        gmma_g(X1Hb, 136, Bb, R0, C0, lm_r, lm_c, acc);
#pragma unroll
        for (int i = 0; i < 2; i++)
#pragma unroll
            for (int j = 0; j < 4; j++) {
                int cl = C0 + 8*j + 2*tg;
                int cg_ = nc*128 + cl;
                float b0 = bf1[cg_], b1 = bf1[cg_+1];
                int lr0 = R0 + 16*i + g, lr1 = lr0 + 8;
                __half2 v0 = __floats2half2_rn(fmaxf(acc[i][j][0]+b0, 0.f), fmaxf(acc[i][j][1]+b1, 0.f));
                __half2 v1 = __floats2half2_rn(fmaxf(acc[i][j][2]+b0, 0.f), fmaxf(acc[i][j][3]+b1, 0.f));
                *reinterpret_cast<uint32_t*>(&ffh[lr0*520 + cg_]) = *reinterpret_cast<uint32_t*>(&v0);
                *reinterpret_cast<uint32_t*>(&ffh[lr1*520 + cg_]) = *reinterpret_cast<uint32_t*>(&v1);
            }
    }
    __syncthreads();

    // ---- stage C
    zacc(acc);
    for (int c = 0; c < 4; c++) {
        int kb = c << 7;
        __syncthreads();
#pragma unroll
        for (int it = 0; it < 8; it++) {
            int idx = tid + it * 256;
            int r = idx >> 4, c8 = idx & 15;
            cp16(Bb + (uint32_t)((r*136 + c8*8)*2), g_wf2 + (long)(kb + r)*128 + c8*8);
        }
        cp_commit(); cp_wait();
        __syncthreads();
        gmma_g(FFHb + (uint32_t)(kb*2), 520, Bb, R0, C0, lm_r, lm_c, acc);
    }
#pragma unroll
    for (int i = 0; i < 2; i++)
#pragma unroll
        for (int j = 0; j < 4; j++) {
            int cl = C0 + 8*j + 2*tg;
            float b0 = bf2[cl], b1 = bf2[cl+1];
            int lr0 = R0 + 16*i + g, lr1 = lr0 + 8;
            float2 r0v = *(const float2*)&x1f[lr0*128 + cl];
            float2 r1v = *(const float2*)&x1f[lr1*128 + cl];
            *(float2*)&Cs[lr0*132 + cl] = make_float2(acc[i][j][0]+b0+r0v.x, acc[i][j][1]+b1+r0v.y);
            *(float2*)&Cs[lr1*132 + cl] = make_float2(acc[i][j][2]+b0+r1v.x, acc[i][j][3]+b1+r1v.y);
        }
    __syncthreads();
#pragma unroll
    for (int r = 0; r < 8; r++) {
        int row = wid * 8 + r;
        float4 v = *(const float4*)&Cs[row*132 + lane*4];
        float s = v.x + v.y + v.z + v.w;
#pragma unroll
        for (int o = 16; o > 0; o >>= 1) s += __shfl_xor_sync(0xffffffffu, s, o);
        float mean = s * (1.f/128.f);
        float4 dd = make_float4(v.x-mean, v.y-mean, v.z-mean, v.w-mean);
        float q = dd.x*dd.x + dd.y*dd.y + dd.z*dd.z + dd.w*dd.w;
#pragma unroll
        for (int o = 16; o > 0; o >>= 1) q += __shfl_xor_sync(0xffffffffu, q, o);
        float rs = rsqrtf(q * (1.f/128.f) + 1e-5f);
        float4 gg = ((const float4*)g2)[lane];
        float4 bb = ((const float4*)be2)[lane];
        float4 o4 = make_float4(dd.x*rs*gg.x+bb.x, dd.y*rs*gg.y+bb.y,
                                dd.z*rs*gg.z+bb.z, dd.w*rs*gg.w+bb.w);
        *(float4*)&out_x[((long)rowbase + row)*128 + lane*4] = o4;
        __half2 ha = __floats2half2_rn(o4.x, o4.y);
        __half2 hb = __floats2half2_rn(o4.z, o4.w);
        uint2 u;
        u.x = *reinterpret_cast<uint32_t*>(&ha);
        u.y = *reinterpret_cast<uint32_t*>(&hb);
        *reinterpret_cast<uint2*>(&x1h[row*136 + lane*4]) = u;
    }
    __syncthreads();

    // ---- stage D: xi = x2@Wei + bedge ; xj = x2@Wej
    for (int which = 0; which < 2; which++) {
        if (which) __syncthreads();
#pragma unroll
        for (int it = 0; it < 8; it++) {
            int idx = tid + it * 256;
            int r = idx >> 4, c8 = idx & 15;
            cp16(Bb + (uint32_t)((r*136 + c8*8)*2),
                 (which ? g_wej : g_wei) + r*128 + c8*8);
        }
        cp_commit(); cp_wait();
        __syncthreads();
        zacc(acc);
        gmma_g(X1Hb, 136, Bb, R0, C0, lm_r, lm_c, acc);
        float* dst = which ? g_xj : g_xi;
#pragma unroll
        for (int i = 0; i < 2; i++)
#pragma unroll
            for (int j = 0; j < 4; j++) {
                int cl = C0 + 8*j + 2*tg;
                float b0 = which ? 0.f : bedge[cl];
                float b1 = which ? 0.f : bedge[cl+1];
                int lr0 = R0 + 16*i + g, lr1 = lr0 + 8;
                *(float2*)&dst[((long)rowbase + lr0)*128 + cl] =
                    make_float2(acc[i][j][0] + b0, acc[i][j][1] + b1);
                *(float2*)&dst[((long)rowbase + lr1)*128 + cl] =
                    make_float2(acc[i][j][2] + b0, acc[i][j][3] + b1);
            }
    }
}

// ---------------- edge_out broadcast: dst = xi[i] + xj[j], 4 float4/thread ----------------
__global__ void __launch_bounds__(256) edge_out_kernel(float* __restrict__ dst) {
    long base = (long)blockIdx.x * 1024 + threadIdx.x;
#pragma unroll
    for (int it = 0; it < 4; it++) {
        long gid = base + it * 256;       // float4 index
        int e4 = (int)(gid & 31);
        long rem = gid >> 5;
        int j = (int)(rem % NN);
        long rem2 = rem / NN;
        int i = (int)(rem2 % NN);
        int b = (int)(rem2 / NN);
        float4 xi = __ldg(&((const float4*)g_xi)[(b * NN + i) * 32 + e4]);
        float4 xj = __ldg(&((const float4*)g_xj)[(b * NN + j) * 32 + e4]);
        float4 o;
        o.x = xi.x + xj.x;
        o.y = xi.y + xj.y;
        o.z = xi.z + xj.z;
        o.w = xi.w + xj.w;
        __stcs(&((float4*)dst)[gid], o);
    }
}

// ---------------- launch ----------------
extern "C" void kernel_launch(void* const* d_in, const int* in_sizes, int n_in,
                              void* d_out, int out_size) {
    const float* node   = (const float*)d_in[0];
    const float* edge   = (const float*)d_in[1];
    const float* Wqi = (const float*)d_in[2];  const float* bqi = (const float*)d_in[3];
    const float* Wki = (const float*)d_in[4];  const float* bki = (const float*)d_in[5];
    const float* Wvi = (const float*)d_in[6];  const float* bvi = (const float*)d_in[7];
    const float* Wqo = (const float*)d_in[8];  const float* bqo = (const float*)d_in[9];
    const float* Wko = (const float*)d_in[10]; const float* bko = (const float*)d_in[11];
    const float* Wvo = (const float*)d_in[12]; const float* bvo = (const float*)d_in[13];
    const float* Wpi = (const float*)d_in[14]; const float* bpi = (const float*)d_in[15];
    const float* Wpo = (const float*)d_in[16]; const float* bpo = (const float*)d_in[17];
    const float* Wf1 = (const float*)d_in[18]; const float* bf1 = (const float*)d_in[19];
    const float* Wf2 = (const float*)d_in[20]; const float* bf2 = (const float*)d_in[21];
    const float* g1  = (const float*)d_in[22]; const float* be1 = (const float*)d_in[23];
    const float* g2  = (const float*)d_in[24]; const float* be2 = (const float*)d_in[25];
    const float* Wedge = (const float*)d_in[26];
    const float* bedge = (const float*)d_in[27];
    float* out = (float*)d_out;

    cudaFuncSetAttribute(fused_edge_kernel,
                         cudaFuncAttributeMaxDynamicSharedMemorySize, 104448);
    cudaFuncSetAttribute(wsum_kernel,
                         cudaFuncAttributeMaxDynamicSharedMemorySize, WSM_TOTAL);
    cudaFuncSetAttribute(node_chain_kernel,
                         cudaFuncAttributeMaxDynamicSharedMemorySize, NSM_TOTAL);

    // precompute
    cvtw_kernel<<<dim3(256, 10), 256>>>(Wqi, Wki, Wqo, Wko, Wf1, Wf2, Wedge, Wpi, Wpo);
    cbias_kernel<<<1, 128>>>(bvi, Wpi, bpi, bvo, Wpo, bpo);

    // 1) q/k projections + scores + fp16 edge spill
    fused_edge_kernel<<<ROWS_TOTAL / 128, 256, 104448>>>(edge, bqi, bki, bqo, bko);

    // 2) softmax + weighted edge sums + headwise @Wv (both directions)
    wsum_kernel<<<dim3(BB * NN, 2), 256, WSM_TOTAL>>>(Wvi, Wvo);

    // 3) full node chain (bedge folded into xi)
    node_chain_kernel<<<BB * NN / 64, 256, NSM_TOTAL>>>(node, bf1, bf2, g1, be1, g2, be2,
                                                        bedge, out);

    // 4) edge_out broadcast
    edge_out_kernel<<<(BB * NN * NN * DD / 4) / 1024, 256>>>(out + BB * NN * DD);
}